// round 4
// baseline (speedup 1.0000x reference)
#include <cuda_runtime.h>
#include <math.h>

#define MAXN 100000
#define CAP  128
#define NEG_SLOPE 0.2f
#define BN_EPS 1e-5f
#define RECON_W 0.1f

typedef unsigned long long ull;

// ---------------- scratch (device globals) ----------------------------------
__device__ float g_h1 [MAXN * 128];   // x @ W1
__device__ float g_h1p[MAXN * 128];   // after GAT1 + BN + ELU
__device__ float g_h2 [MAXN * 32];    // h1p @ W2
__device__ float g_o2 [MAXN * 32];    // after GAT2 + bias
__device__ float g_as1[MAXN * 4];
__device__ float g_ad1[MAXN * 4];
__device__ float g_as2[MAXN];
__device__ float g_ad2[MAXN];
__device__ int   g_deg[MAXN];         // zeroed invariant: reset by k_gat2
__device__ int   g_csr[MAXN * CAP];   // per-dst src lists (bucketed)

__device__ __forceinline__ float lrelu(float t) { return t > 0.f ? t : NEG_SLOPE * t; }

// ---- packed f32x2 helpers ---------------------------------------------------
__device__ __forceinline__ ull pk2(float lo, float hi) {
    ull r;
    asm("mov.b64 %0, {%1, %2};" : "=l"(r) : "r"(__float_as_uint(lo)), "r"(__float_as_uint(hi)));
    return r;
}
__device__ __forceinline__ ull splat2(float v) { return pk2(v, v); }
__device__ __forceinline__ void fma2(ull& d, ull a, ull b) {
    asm("fma.rn.f32x2 %0, %1, %2, %0;" : "+l"(d) : "l"(a), "l"(b));
}
__device__ __forceinline__ float2 upk2(ull v) {
    unsigned lo, hi;
    asm("mov.b64 {%0, %1}, %2;" : "=r"(lo), "=r"(hi) : "l"(v));
    return make_float2(__uint_as_float(lo), __uint_as_float(hi));
}

// ---------------- adjacency build -------------------------------------------
__global__ void k_fill(const int* __restrict__ ei, int E) {
    int e = blockIdx.x * blockDim.x + threadIdx.x;
    if (e >= E) return;
    int s = ei[e], d = ei[E + e];
    int pos = atomicAdd(&g_deg[d], 1);
    if (pos < CAP) g_csr[d * CAP + pos] = s;
}

// ============================================================================
// GEMM1: g_h1[N,128] = x[N,128] @ W1[128,128], fused alpha1 epilogue.
// 256 threads, tile 128x128, micro 8x8 (f32x2 packed), BK=16, double-buffered.
// ============================================================================
__global__ __launch_bounds__(256) void k_gemm1(
    const float* __restrict__ A, const float* __restrict__ B,
    const float* __restrict__ avs, const float* __restrict__ avd, int Nrows)
{
    __shared__ float Xs[2][16][128];
    __shared__ float Ws[2][16][128];
    int t  = threadIdx.x;
    int tx = t & 15, ty = t >> 4;
    int r0 = blockIdx.x * 128;

    int ar = t & 127, aq = t >> 7;           // A: row ar, col-octet aq
    int bk0 = t >> 5, bc4 = t & 31;          // B: rows bk0 & bk0+8, float4 bc4

    bool aval = (r0 + ar) < Nrows;
    const float* Abase = A + (size_t)(r0 + ar) * 128 + aq * 8;

    {
        float4 v0 = aval ? *(const float4*)(Abase + 0) : make_float4(0,0,0,0);
        float4 v1 = aval ? *(const float4*)(Abase + 4) : make_float4(0,0,0,0);
        Xs[0][aq*8+0][ar] = v0.x; Xs[0][aq*8+1][ar] = v0.y;
        Xs[0][aq*8+2][ar] = v0.z; Xs[0][aq*8+3][ar] = v0.w;
        Xs[0][aq*8+4][ar] = v1.x; Xs[0][aq*8+5][ar] = v1.y;
        Xs[0][aq*8+6][ar] = v1.z; Xs[0][aq*8+7][ar] = v1.w;
        *(float4*)&Ws[0][bk0    ][bc4*4] = *(const float4*)&B[(bk0    ) * 128 + bc4*4];
        *(float4*)&Ws[0][bk0 + 8][bc4*4] = *(const float4*)&B[(bk0 + 8) * 128 + bc4*4];
    }
    __syncthreads();

    ull acc2[8][4];
#pragma unroll
    for (int i = 0; i < 8; i++)
#pragma unroll
        for (int j = 0; j < 4; j++) acc2[i][j] = 0ull;

    int buf = 0;
    for (int kb = 0; kb < 128; kb += 16) {
        bool has_next = (kb + 16) < 128;
        float4 aR0, aR1, bR0, bR1;
        if (has_next) {
            aR0 = aval ? *(const float4*)(Abase + kb + 16 + 0) : make_float4(0,0,0,0);
            aR1 = aval ? *(const float4*)(Abase + kb + 16 + 4) : make_float4(0,0,0,0);
            bR0 = *(const float4*)&B[(kb + 16 + bk0    ) * 128 + bc4*4];
            bR1 = *(const float4*)&B[(kb + 16 + bk0 + 8) * 128 + bc4*4];
        }
#pragma unroll
        for (int kk = 0; kk < 16; kk++) {
            float4 a0 = *(const float4*)&Xs[buf][kk][ty*8];
            float4 a1 = *(const float4*)&Xs[buf][kk][ty*8 + 4];
            ulonglong2 w01 = *(const ulonglong2*)&Ws[buf][kk][tx*8];
            ulonglong2 w23 = *(const ulonglong2*)&Ws[buf][kk][tx*8 + 4];
            float av[8] = {a0.x,a0.y,a0.z,a0.w,a1.x,a1.y,a1.z,a1.w};
#pragma unroll
            for (int i = 0; i < 8; i++) {
                ull ai = splat2(av[i]);
                fma2(acc2[i][0], ai, w01.x);
                fma2(acc2[i][1], ai, w01.y);
                fma2(acc2[i][2], ai, w23.x);
                fma2(acc2[i][3], ai, w23.y);
            }
        }
        if (has_next) {
            int nb = buf ^ 1;
            Xs[nb][aq*8+0][ar] = aR0.x; Xs[nb][aq*8+1][ar] = aR0.y;
            Xs[nb][aq*8+2][ar] = aR0.z; Xs[nb][aq*8+3][ar] = aR0.w;
            Xs[nb][aq*8+4][ar] = aR1.x; Xs[nb][aq*8+5][ar] = aR1.y;
            Xs[nb][aq*8+6][ar] = aR1.z; Xs[nb][aq*8+7][ar] = aR1.w;
            *(float4*)&Ws[nb][bk0    ][bc4*4] = bR0;
            *(float4*)&Ws[nb][bk0 + 8][bc4*4] = bR1;
        }
        __syncthreads();
        buf ^= 1;
    }

    float as[8], ad[8];
    {
        float4 s0 = *(const float4*)&avs[tx*8], s1 = *(const float4*)&avs[tx*8 + 4];
        float4 d0 = *(const float4*)&avd[tx*8], d1 = *(const float4*)&avd[tx*8 + 4];
        as[0]=s0.x; as[1]=s0.y; as[2]=s0.z; as[3]=s0.w; as[4]=s1.x; as[5]=s1.y; as[6]=s1.z; as[7]=s1.w;
        ad[0]=d0.x; ad[1]=d0.y; ad[2]=d0.z; ad[3]=d0.w; ad[4]=d1.x; ad[5]=d1.y; ad[6]=d1.z; ad[7]=d1.w;
    }

#pragma unroll
    for (int i = 0; i < 8; i++) {
        int gr = r0 + ty*8 + i;
        if (gr >= Nrows) break;
        // store 8 floats (packed pairs are contiguous)
        *(ulonglong2*)&g_h1[(size_t)gr*128 + tx*8    ] = make_ulonglong2(acc2[i][0], acc2[i][1]);
        *(ulonglong2*)&g_h1[(size_t)gr*128 + tx*8 + 4] = make_ulonglong2(acc2[i][2], acc2[i][3]);
        float c[8];
#pragma unroll
        for (int q = 0; q < 4; q++) {
            float2 f = upk2(acc2[i][q]);
            c[q*2] = f.x; c[q*2+1] = f.y;
        }
        float ps = 0.f, pd = 0.f;
#pragma unroll
        for (int j = 0; j < 8; j++) { ps = fmaf(c[j], as[j], ps); pd = fmaf(c[j], ad[j], pd); }
        ps += __shfl_xor_sync(0xffffffffu, ps, 1);
        pd += __shfl_xor_sync(0xffffffffu, pd, 1);
        ps += __shfl_xor_sync(0xffffffffu, ps, 2);
        pd += __shfl_xor_sync(0xffffffffu, pd, 2);
        if ((tx & 3) == 0) {
            g_as1[gr*4 + (tx >> 2)] = ps;
            g_ad1[gr*4 + (tx >> 2)] = pd;
        }
    }
}

// ============================================================================
// GEMM2: g_h2[N,32] = g_h1p[N,128] @ W2[128,32], fused alpha2 epilogue.
// 256 threads, tile 256x32, micro 8x4 (f32x2 packed), BK=16, double-buffered.
// ============================================================================
__global__ __launch_bounds__(256) void k_gemm2(
    const float* __restrict__ B,
    const float* __restrict__ avs, const float* __restrict__ avd, int Nrows)
{
    __shared__ float Xs[2][16][256];
    __shared__ float Ws[2][16][32];
    const float* A = g_h1p;
    int t  = threadIdx.x;
    int tx = t & 7, ty = t >> 3;
    int r0 = blockIdx.x * 256;

    bool aval = (r0 + t) < Nrows;
    const float* Abase = A + (size_t)(r0 + t) * 128;
    int bk0 = t >> 3, bc4 = t & 7;

    {
#pragma unroll
        for (int q = 0; q < 4; q++) {
            float4 v = aval ? *(const float4*)(Abase + q*4) : make_float4(0,0,0,0);
            Xs[0][q*4+0][t] = v.x; Xs[0][q*4+1][t] = v.y;
            Xs[0][q*4+2][t] = v.z; Xs[0][q*4+3][t] = v.w;
        }
        if (t < 128) *(float4*)&Ws[0][bk0][bc4*4] = *(const float4*)&B[bk0*32 + bc4*4];
    }
    __syncthreads();

    ull acc2[8][2];
#pragma unroll
    for (int i = 0; i < 8; i++) { acc2[i][0] = 0ull; acc2[i][1] = 0ull; }

    int buf = 0;
    for (int kb = 0; kb < 128; kb += 16) {
        bool has_next = (kb + 16) < 128;
        float4 aR[4]; float4 bR;
        if (has_next) {
#pragma unroll
            for (int q = 0; q < 4; q++)
                aR[q] = aval ? *(const float4*)(Abase + kb + 16 + q*4) : make_float4(0,0,0,0);
            if (t < 128) bR = *(const float4*)&B[(kb + 16 + bk0)*32 + bc4*4];
        }
#pragma unroll
        for (int kk = 0; kk < 16; kk++) {
            float4 a0 = *(const float4*)&Xs[buf][kk][ty*8];
            float4 a1 = *(const float4*)&Xs[buf][kk][ty*8 + 4];
            ulonglong2 w01 = *(const ulonglong2*)&Ws[buf][kk][tx*4];
            float av[8] = {a0.x,a0.y,a0.z,a0.w,a1.x,a1.y,a1.z,a1.w};
#pragma unroll
            for (int i = 0; i < 8; i++) {
                ull ai = splat2(av[i]);
                fma2(acc2[i][0], ai, w01.x);
                fma2(acc2[i][1], ai, w01.y);
            }
        }
        if (has_next) {
            int nb = buf ^ 1;
#pragma unroll
            for (int q = 0; q < 4; q++) {
                Xs[nb][q*4+0][t] = aR[q].x; Xs[nb][q*4+1][t] = aR[q].y;
                Xs[nb][q*4+2][t] = aR[q].z; Xs[nb][q*4+3][t] = aR[q].w;
            }
            if (t < 128) *(float4*)&Ws[nb][bk0][bc4*4] = bR;
        }
        __syncthreads();
        buf ^= 1;
    }

    float4 s0 = *(const float4*)&avs[tx*4];
    float4 d0 = *(const float4*)&avd[tx*4];
    float as[4] = {s0.x,s0.y,s0.z,s0.w};
    float ad[4] = {d0.x,d0.y,d0.z,d0.w};

#pragma unroll
    for (int i = 0; i < 8; i++) {
        int gr = r0 + ty*8 + i;
        if (gr >= Nrows) break;
        *(ulonglong2*)&g_h2[(size_t)gr*32 + tx*4] = make_ulonglong2(acc2[i][0], acc2[i][1]);
        float2 f0 = upk2(acc2[i][0]), f1 = upk2(acc2[i][1]);
        float c[4] = {f0.x, f0.y, f1.x, f1.y};
        float ps = 0.f, pd = 0.f;
#pragma unroll
        for (int j = 0; j < 4; j++) { ps = fmaf(c[j], as[j], ps); pd = fmaf(c[j], ad[j], pd); }
        ps += __shfl_xor_sync(0xffffffffu, ps, 1);
        pd += __shfl_xor_sync(0xffffffffu, pd, 1);
        ps += __shfl_xor_sync(0xffffffffu, ps, 2);
        pd += __shfl_xor_sync(0xffffffffu, pd, 2);
        ps += __shfl_xor_sync(0xffffffffu, ps, 4);
        pd += __shfl_xor_sync(0xffffffffu, pd, 4);
        if (tx == 0) { g_as2[gr] = ps; g_ad2[gr] = pd; }
    }
}

// ---------------- GAT1 gather: warp per dst node ----------------------------
// Weights for a 32-edge chunk are precomputed one-edge-per-lane into shared,
// then the inner loop is shfl + LDS + packed FMA.
__global__ __launch_bounds__(256) void k_gat1(
    const float* __restrict__ b1,
    const float* __restrict__ bg, const float* __restrict__ bb,
    const float* __restrict__ bm, const float* __restrict__ bv, int N)
{
    __shared__ float ws[8][32][4];
    int wid  = threadIdx.x >> 5;
    int lane = threadIdx.x & 31;
    int d    = blockIdx.x * 8 + wid;
    if (d >= N) return;
    int head = lane >> 3;

    float4 adv4 = *(const float4*)&g_ad1[d * 4];
    float advh  = head == 0 ? adv4.x : head == 1 ? adv4.y : head == 2 ? adv4.z : adv4.w;

    // self-loop
    float4 asf = *(const float4*)&g_as1[d * 4];
    float ash  = head == 0 ? asf.x : head == 1 ? asf.y : head == 2 ? asf.z : asf.w;
    float wself = __expf(lrelu(ash + advh));
    ulonglong2 hv = *(const ulonglong2*)&g_h1[(size_t)d * 128 + lane * 4];
    ull wv = splat2(wself);
    ull acc0 = 0ull, acc1 = 0ull;
    fma2(acc0, wv, hv.x);
    fma2(acc1, wv, hv.y);
    float wsum = wself;

    int deg = min(g_deg[d], CAP);
    const int* lst = &g_csr[d * CAP];
    for (int j0 = 0; j0 < deg; j0 += 32) {
        int m = min(32, deg - j0);
        int sid = (lane < m) ? lst[j0 + lane] : 0;
        if (lane < m) {
            float4 a4 = __ldg((const float4*)&g_as1[sid * 4]);
            float4 w4;
            w4.x = __expf(lrelu(a4.x + adv4.x));
            w4.y = __expf(lrelu(a4.y + adv4.y));
            w4.z = __expf(lrelu(a4.z + adv4.z));
            w4.w = __expf(lrelu(a4.w + adv4.w));
            *(float4*)&ws[wid][lane][0] = w4;
        }
        __syncwarp();
#pragma unroll 4
        for (int jj = 0; jj < m; jj++) {
            int s = __shfl_sync(0xffffffffu, sid, jj);
            float w = ws[wid][jj][head];
            ulonglong2 h = *(const ulonglong2*)&g_h1[(size_t)s * 128 + lane * 4];
            ull w2 = splat2(w);
            fma2(acc0, w2, h.x);
            fma2(acc1, w2, h.y);
            wsum += w;
        }
        __syncwarp();
    }

    float inv = 1.f / wsum;
    float2 f0 = upk2(acc0), f1 = upk2(acc1);
    float4 av = make_float4(f0.x, f0.y, f1.x, f1.y);
    float4 bc = *(const float4*)&b1[lane * 4];
    float4 g4 = *(const float4*)&bg[lane * 4];
    float4 b4 = *(const float4*)&bb[lane * 4];
    float4 m4 = *(const float4*)&bm[lane * 4];
    float4 v4 = *(const float4*)&bv[lane * 4];
    float4 o;
    o.x = (av.x * inv + bc.x - m4.x) * rsqrtf(v4.x + BN_EPS) * g4.x + b4.x;
    o.y = (av.y * inv + bc.y - m4.y) * rsqrtf(v4.y + BN_EPS) * g4.y + b4.y;
    o.z = (av.z * inv + bc.z - m4.z) * rsqrtf(v4.z + BN_EPS) * g4.z + b4.z;
    o.w = (av.w * inv + bc.w - m4.w) * rsqrtf(v4.w + BN_EPS) * g4.w + b4.w;
    o.x = o.x > 0.f ? o.x : expm1f(o.x);
    o.y = o.y > 0.f ? o.y : expm1f(o.y);
    o.z = o.z > 0.f ? o.z : expm1f(o.z);
    o.w = o.w > 0.f ? o.w : expm1f(o.w);
    *(float4*)&g_h1p[(size_t)d * 128 + lane * 4] = o;
}

// ---------------- GAT2 gather: warp per dst node (C=32, 1 head) -------------
// Also resets g_deg (zeroed invariant for graph replay).
__global__ __launch_bounds__(256) void k_gat2(const float* __restrict__ b2, int N) {
    int gw   = (blockIdx.x * blockDim.x + threadIdx.x) >> 5;
    int lane = threadIdx.x & 31;
    if (gw >= N) return;
    int d = gw;

    float adv = __ldg(&g_ad2[d]);
    float w = __expf(lrelu(__ldg(&g_as2[d]) + adv));
    float acc = w * g_h2[(size_t)d * 32 + lane];
    float wsum = w;

    int deg = min(g_deg[d], CAP);
    const int* lst = &g_csr[d * CAP];
    for (int j0 = 0; j0 < deg; j0 += 32) {
        int m = min(32, deg - j0);
        int sid = (lane < m) ? lst[j0 + lane] : 0;
        float wl = (lane < m) ? __expf(lrelu(__ldg(&g_as2[sid]) + adv)) : 0.f;
#pragma unroll 4
        for (int jj = 0; jj < m; jj++) {
            int s  = __shfl_sync(0xffffffffu, sid, jj);
            float we = __shfl_sync(0xffffffffu, wl, jj);
            acc = fmaf(we, __ldg(&g_h2[(size_t)s * 32 + lane]), acc);
            wsum += we;
        }
    }
    g_o2[(size_t)d * 32 + lane] = acc / wsum + __ldg(&b2[lane]);
    if (lane == 0) g_deg[d] = 0;
}

// ---------------- final: per-node MLP tail + log_softmax --------------------
__global__ void k_final(const float* __restrict__ ctx,
                        const float* __restrict__ rw1, const float* __restrict__ rb1,
                        const float* __restrict__ rw2, const float* __restrict__ rb2,
                        const float* __restrict__ dw,  const float* __restrict__ db,
                        const float* __restrict__ cw,  const float* __restrict__ cb,
                        float* __restrict__ out, int N) {
    __shared__ float sw[2666];
    int t = threadIdx.x;
    for (int i = t; i < 192;  i += 256) sw[i]        = rw1[i];
    for (int i = t; i < 32;   i += 256) sw[192 + i]  = rb1[i];
    for (int i = t; i < 1024; i += 256) sw[224 + i]  = rw2[i];
    for (int i = t; i < 32;   i += 256) sw[1248 + i] = rb2[i];
    for (int i = t; i < 1024; i += 256) sw[1280 + i] = dw[i];
    for (int i = t; i < 32;   i += 256) sw[2304 + i] = db[i];
    for (int i = t; i < 320;  i += 256) sw[2336 + i] = cw[i];
    for (int i = t; i < 10;   i += 256) sw[2656 + i] = cb[i];
    __syncthreads();

    int n = blockIdx.x * 256 + t;
    if (n >= N) return;

    float c0 = ctx[n * 6 + 0], c1 = ctx[n * 6 + 1], c2 = ctx[n * 6 + 2];
    float c3 = ctx[n * 6 + 3], c4 = ctx[n * 6 + 4], c5 = ctx[n * 6 + 5];

    float t1[32];
#pragma unroll
    for (int j = 0; j < 32; j++) {
        float v = sw[192 + j];
        v = fmaf(c0, sw[0 * 32 + j], v);
        v = fmaf(c1, sw[1 * 32 + j], v);
        v = fmaf(c2, sw[2 * 32 + j], v);
        v = fmaf(c3, sw[3 * 32 + j], v);
        v = fmaf(c4, sw[4 * 32 + j], v);
        v = fmaf(c5, sw[5 * 32 + j], v);
        t1[j] = fmaxf(v, 0.f);
    }
    float ex[32];
#pragma unroll
    for (int j = 0; j < 32; j++) {
        float v = sw[1248 + j];
#pragma unroll
        for (int k = 0; k < 32; k++) v = fmaf(t1[k], sw[224 + k * 32 + j], v);
        ex[j] = v;
    }
    float comb[32];
#pragma unroll
    for (int j = 0; j < 32; j++) {
        float rec = sw[2304 + j];
#pragma unroll
        for (int k = 0; k < 32; k++) rec = fmaf(ex[k], sw[1280 + k * 32 + j], rec);
        comb[j] = g_o2[(size_t)n * 32 + j] + RECON_W * rec;
    }
    float lg[10];
#pragma unroll
    for (int c = 0; c < 10; c++) {
        float v = sw[2656 + c];
#pragma unroll
        for (int j = 0; j < 32; j++) v = fmaf(comb[j], sw[2336 + j * 10 + c], v);
        lg[c] = v;
    }
    float m = lg[0];
#pragma unroll
    for (int c = 1; c < 10; c++) m = fmaxf(m, lg[c]);
    float sum = 0.f;
#pragma unroll
    for (int c = 0; c < 10; c++) sum += expf(lg[c] - m);
    float lse = m + logf(sum);
#pragma unroll
    for (int c = 0; c < 10; c++) out[n * 10 + c] = lg[c] - lse;
#pragma unroll
    for (int j = 0; j < 32; j++) out[N * 10 + n * 32 + j] = ex[j];
}

// ---------------- launch -----------------------------------------------------
extern "C" void kernel_launch(void* const* d_in, const int* in_sizes, int n_in,
                              void* d_out, int out_size) {
    const float* x    = (const float*)d_in[0];
    const int*   ei   = (const int*)  d_in[1];
    const float* ctx  = (const float*)d_in[2];
    const float* W1   = (const float*)d_in[3];
    const float* as1  = (const float*)d_in[4];
    const float* ad1  = (const float*)d_in[5];
    const float* b1   = (const float*)d_in[6];
    const float* bng  = (const float*)d_in[7];
    const float* bnb  = (const float*)d_in[8];
    const float* bnm  = (const float*)d_in[9];
    const float* bnv  = (const float*)d_in[10];
    const float* W2   = (const float*)d_in[11];
    const float* as2  = (const float*)d_in[12];
    const float* ad2  = (const float*)d_in[13];
    const float* b2   = (const float*)d_in[14];
    const float* rw1  = (const float*)d_in[15];
    const float* rb1  = (const float*)d_in[16];
    const float* rw2  = (const float*)d_in[17];
    const float* rb2  = (const float*)d_in[18];
    const float* dw   = (const float*)d_in[19];
    const float* db   = (const float*)d_in[20];
    const float* cw   = (const float*)d_in[21];
    const float* cb   = (const float*)d_in[22];
    float* out = (float*)d_out;

    int N = in_sizes[0] / 128;
    int E = in_sizes[1] / 2;

    // adjacency build (g_deg starts/stays zeroed; reset by k_gat2)
    k_fill<<<(E + 255) / 256, 256>>>(ei, E);

    // layer 1: GEMM + fused alpha, then gather
    k_gemm1<<<(N + 127) / 128, 256>>>(x, W1, as1, ad1, N);
    k_gat1<<<(N + 7) / 8, 256>>>(b1, bng, bnb, bnm, bnv, N);

    // layer 2
    k_gemm2<<<(N + 255) / 256, 256>>>(W2, as2, ad2, N);
    k_gat2<<<(N * 32 + 255) / 256, 256>>>(b2, N);

    k_final<<<(N + 255) / 256, 256>>>(ctx, rw1, rb1, rw2, rb2, dw, db, cw, cb,
                                      out, N);
}

// round 6
// speedup vs baseline: 1.0931x; 1.0931x over previous
#include <cuda_runtime.h>
#include <cuda_bf16.h>
#include <math.h>

#define MAXN 100000
#define CAP  128
#define NEG_SLOPE 0.2f
#define BN_EPS 1e-5f
#define RECON_W 0.1f

// ---------------- scratch (device globals) ----------------------------------
__device__ float g_h1 [MAXN * 128];   // x @ W1
__device__ float g_h1p[MAXN * 128];   // after GAT1 + BN + ELU
__device__ float g_h2 [MAXN * 32];    // h1p @ W2
__device__ float g_o2 [MAXN * 32];    // after GAT2 + bias
__device__ float g_as1[MAXN * 4];
__device__ float g_ad1[MAXN * 4];
__device__ float g_as2[MAXN];
__device__ float g_ad2[MAXN];
__device__ int   g_deg[MAXN];         // zeroed invariant: reset by k_gat2
__device__ int   g_csr[MAXN * CAP];   // per-dst src lists (bucketed)
__device__ __nv_bfloat16 g_w1hi[128 * 136];  // W1^T bf16 hi, n-major padded
__device__ __nv_bfloat16 g_w1lo[128 * 136];  // W1^T bf16 lo, n-major padded

__device__ __forceinline__ float lrelu(float t) { return t > 0.f ? t : NEG_SLOPE * t; }

__device__ __forceinline__ unsigned s2u(const void* p) {
    unsigned a;
    asm("{ .reg .u64 t; cvta.to.shared.u64 t, %1; cvt.u32.u64 %0, t; }" : "=r"(a) : "l"(p));
    return a;
}

#define LDSM4(f, addr) \
    asm volatile("ldmatrix.sync.aligned.m8n8.x4.shared.b16 {%0,%1,%2,%3}, [%4];" \
        : "=r"((f)[0]),"=r"((f)[1]),"=r"((f)[2]),"=r"((f)[3]) : "r"(addr))

#define MMA_BF16(dd, a, b0, b1) \
    asm volatile("mma.sync.aligned.m16n8k16.row.col.f32.bf16.bf16.f32 " \
        "{%0,%1,%2,%3}, {%4,%5,%6,%7}, {%8,%9}, {%0,%1,%2,%3};" \
        : "+f"((dd)[0]),"+f"((dd)[1]),"+f"((dd)[2]),"+f"((dd)[3]) \
        : "r"((a)[0]),"r"((a)[1]),"r"((a)[2]),"r"((a)[3]), "r"(b0),"r"(b1))

// ---------------- adjacency build -------------------------------------------
__global__ void k_fill(const int* __restrict__ ei, int E) {
    int e = blockIdx.x * blockDim.x + threadIdx.x;
    if (e >= E) return;
    int s = ei[e], d = ei[E + e];
    int pos = atomicAdd(&g_deg[d], 1);
    if (pos < CAP) g_csr[d * CAP + pos] = s;
}

// ---------------- W1 prep: transpose + bf16 hi/lo split, n-major padded -----
__global__ void k_prep_w1(const float* __restrict__ W1) {
    int i = blockIdx.x * 256 + threadIdx.x;   // i = k*128 + n
    int k = i >> 7, n = i & 127;
    float v = W1[i];
    __nv_bfloat16 hi = __float2bfloat16(v);
    __nv_bfloat16 lo = __float2bfloat16(v - __bfloat162float(hi));
    g_w1hi[n * 136 + k] = hi;
    g_w1lo[n * 136 + k] = lo;
}

// ============================================================================
// GEMM1 via mma.sync bf16 (3-chain hi/lo): g_h1[N,128] = x[N,128] @ W1[128,128]
// + fused alpha1 epilogue. 256 threads, 128 rows/CTA, warp w -> rows 16w..16w+15.
// ============================================================================
#define SM_A_ELE (128 * 136)
#define SM_TOT   (4 * SM_A_ELE * 2 + 1024)

__global__ __launch_bounds__(256) void k_gemm1_hmma(
    const float* __restrict__ x,
    const float* __restrict__ avs, const float* __restrict__ avd, int N)
{
    extern __shared__ char sm[];
    __nv_bfloat16* Ahi = (__nv_bfloat16*)sm;
    __nv_bfloat16* Alo = Ahi + SM_A_ELE;
    __nv_bfloat16* Whi = Alo + SM_A_ELE;
    __nv_bfloat16* Wlo = Whi + SM_A_ELE;
    float* s_as = (float*)(Wlo + SM_A_ELE);
    float* s_ad = s_as + 128;

    int t = threadIdx.x;
    int r0 = blockIdx.x * 128;

    // stage W (pre-split/padded in global)
    {
        const float4* shi = (const float4*)g_w1hi;
        const float4* slo = (const float4*)g_w1lo;
        float4* dhi = (float4*)Whi;
        float4* dlo = (float4*)Wlo;
        for (int i = t; i < SM_A_ELE / 8; i += 256) { dhi[i] = shi[i]; dlo[i] = slo[i]; }
    }
    if (t < 128) { s_as[t] = avs[t]; s_ad[t] = avd[t]; }
    // stage A: load x, split hi/lo
    {
        int row = t >> 1, ch = (t & 1) * 64;
        int gr = r0 + row;
        const float* xr = x + (size_t)gr * 128 + ch;
#pragma unroll
        for (int c = 0; c < 64; c += 4) {
            float4 v = (gr < N) ? *(const float4*)(xr + c) : make_float4(0, 0, 0, 0);
            float f[4] = {v.x, v.y, v.z, v.w};
            __nv_bfloat16 h[4], l[4];
#pragma unroll
            for (int q = 0; q < 4; q++) {
                h[q] = __float2bfloat16(f[q]);
                l[q] = __float2bfloat16(f[q] - __bfloat162float(h[q]));
            }
            int eo = row * 136 + ch + c;
            *(__nv_bfloat162*)&Ahi[eo]     = __nv_bfloat162(h[0], h[1]);
            *(__nv_bfloat162*)&Ahi[eo + 2] = __nv_bfloat162(h[2], h[3]);
            *(__nv_bfloat162*)&Alo[eo]     = __nv_bfloat162(l[0], l[1]);
            *(__nv_bfloat162*)&Alo[eo + 2] = __nv_bfloat162(l[2], l[3]);
        }
    }
    __syncthreads();

    int wid = t >> 5, lane = t & 31;
    int j = lane >> 3, rin = lane & 7;

    // fragment base byte offsets (136-elt rows, 2B/elt)
    unsigned aOff = ((unsigned)((wid * 16 + (j & 1) * 8 + rin) * 136 + (j >> 1) * 8)) * 2;
    unsigned bOff = ((unsigned)(((j >> 1) * 8 + rin) * 136 + (j & 1) * 8)) * 2;
    unsigned aHiB = s2u(Ahi) + aOff, aLoB = s2u(Alo) + aOff;
    unsigned wHiB = s2u(Whi) + bOff, wLoB = s2u(Wlo) + bOff;

    float d[16][4];
#pragma unroll
    for (int i = 0; i < 16; i++)
#pragma unroll
        for (int q = 0; q < 4; q++) d[i][q] = 0.f;

#pragma unroll 1
    for (int ks = 0; ks < 8; ks++) {
        unsigned ah[4], al[4];
        LDSM4(ah, aHiB + ks * 32);
        LDSM4(al, aLoB + ks * 32);
#pragma unroll
        for (int p = 0; p < 8; p++) {
            unsigned bh[4], bl[4];
            LDSM4(bh, wHiB + p * 4352 + ks * 32);
            LDSM4(bl, wLoB + p * 4352 + ks * 32);
            MMA_BF16(d[2*p],     ah, bh[0], bh[1]);
            MMA_BF16(d[2*p + 1], ah, bh[2], bh[3]);
            MMA_BF16(d[2*p],     al, bh[0], bh[1]);
            MMA_BF16(d[2*p + 1], al, bh[2], bh[3]);
            MMA_BF16(d[2*p],     ah, bl[0], bl[1]);
            MMA_BF16(d[2*p + 1], ah, bl[2], bl[3]);
        }
    }

    // epilogue: write h1 + fused alpha1 (rows rA = g, rB = g+8 of this warp)
    int g = lane >> 2, t4 = lane & 3;
    int rA = r0 + wid * 16 + g, rB = rA + 8;
    float psA[4] = {0,0,0,0}, pdA[4] = {0,0,0,0};
    float psB[4] = {0,0,0,0}, pdB[4] = {0,0,0,0};
#pragma unroll
    for (int nt = 0; nt < 16; nt++) {
        int n0 = nt * 8 + 2 * t4;
        float w0s = s_as[n0], w1s = s_as[n0 + 1];
        float w0d = s_ad[n0], w1d = s_ad[n0 + 1];
        int h = nt >> 2;
        psA[h] = fmaf(d[nt][0], w0s, fmaf(d[nt][1], w1s, psA[h]));
        pdA[h] = fmaf(d[nt][0], w0d, fmaf(d[nt][1], w1d, pdA[h]));
        psB[h] = fmaf(d[nt][2], w0s, fmaf(d[nt][3], w1s, psB[h]));
        pdB[h] = fmaf(d[nt][2], w0d, fmaf(d[nt][3], w1d, pdB[h]));
        if (rA < N) *(float2*)&g_h1[(size_t)rA * 128 + n0] = make_float2(d[nt][0], d[nt][1]);
        if (rB < N) *(float2*)&g_h1[(size_t)rB * 128 + n0] = make_float2(d[nt][2], d[nt][3]);
    }
#pragma unroll
    for (int h = 0; h < 4; h++) {
        psA[h] += __shfl_xor_sync(0xffffffffu, psA[h], 1);
        pdA[h] += __shfl_xor_sync(0xffffffffu, pdA[h], 1);
        psB[h] += __shfl_xor_sync(0xffffffffu, psB[h], 1);
        pdB[h] += __shfl_xor_sync(0xffffffffu, pdB[h], 1);
        psA[h] += __shfl_xor_sync(0xffffffffu, psA[h], 2);
        pdA[h] += __shfl_xor_sync(0xffffffffu, pdA[h], 2);
        psB[h] += __shfl_xor_sync(0xffffffffu, psB[h], 2);
        pdB[h] += __shfl_xor_sync(0xffffffffu, pdB[h], 2);
    }
    if (t4 == 0) {
        if (rA < N) {
#pragma unroll
            for (int h = 0; h < 4; h++) { g_as1[rA*4 + h] = psA[h]; g_ad1[rA*4 + h] = pdA[h]; }
        }
        if (rB < N) {
#pragma unroll
            for (int h = 0; h < 4; h++) { g_as1[rB*4 + h] = psB[h]; g_ad1[rB*4 + h] = pdB[h]; }
        }
    }
}

// ============================================================================
// GEMM2: g_h2[N,32] = g_h1p[N,128] @ W2[128,32], fused alpha2 epilogue.
// 256 threads, tile 256x32, micro 8x4, BK=16, double-buffered, plain fmaf.
// ============================================================================
__global__ __launch_bounds__(256) void k_gemm2(
    const float* __restrict__ B,
    const float* __restrict__ avs, const float* __restrict__ avd, int Nrows)
{
    __shared__ float Xs[2][16][256];
    __shared__ float Ws[2][16][32];
    const float* A = g_h1p;
    int t  = threadIdx.x;
    int tx = t & 7, ty = t >> 3;
    int r0 = blockIdx.x * 256;

    bool aval = (r0 + t) < Nrows;
    const float* Abase = A + (size_t)(r0 + t) * 128;
    int bk0 = t >> 3, bc4 = t & 7;

    {
#pragma unroll
        for (int q = 0; q < 4; q++) {
            float4 v = aval ? *(const float4*)(Abase + q*4) : make_float4(0,0,0,0);
            Xs[0][q*4+0][t] = v.x; Xs[0][q*4+1][t] = v.y;
            Xs[0][q*4+2][t] = v.z; Xs[0][q*4+3][t] = v.w;
        }
        if (t < 128) *(float4*)&Ws[0][bk0][bc4*4] = *(const float4*)&B[bk0*32 + bc4*4];
    }
    __syncthreads();

    float acc[8][4];
#pragma unroll
    for (int i = 0; i < 8; i++)
#pragma unroll
        for (int j = 0; j < 4; j++) acc[i][j] = 0.f;

    int buf = 0;
    for (int kb = 0; kb < 128; kb += 16) {
        bool has_next = (kb + 16) < 128;
        float4 aR[4]; float4 bR;
        if (has_next) {
#pragma unroll
            for (int q = 0; q < 4; q++)
                aR[q] = aval ? *(const float4*)(Abase + kb + 16 + q*4) : make_float4(0,0,0,0);
            if (t < 128) bR = *(const float4*)&B[(kb + 16 + bk0)*32 + bc4*4];
        }
#pragma unroll
        for (int kk = 0; kk < 16; kk++) {
            float4 a0 = *(const float4*)&Xs[buf][kk][ty*8];
            float4 a1 = *(const float4*)&Xs[buf][kk][ty*8 + 4];
            float4 b0 = *(const float4*)&Ws[buf][kk][tx*4];
            float av[8] = {a0.x,a0.y,a0.z,a0.w,a1.x,a1.y,a1.z,a1.w};
            float bv[4] = {b0.x,b0.y,b0.z,b0.w};
#pragma unroll
            for (int i = 0; i < 8; i++)
#pragma unroll
                for (int j = 0; j < 4; j++) acc[i][j] = fmaf(av[i], bv[j], acc[i][j]);
        }
        if (has_next) {
            int nb = buf ^ 1;
#pragma unroll
            for (int q = 0; q < 4; q++) {
                Xs[nb][q*4+0][t] = aR[q].x; Xs[nb][q*4+1][t] = aR[q].y;
                Xs[nb][q*4+2][t] = aR[q].z; Xs[nb][q*4+3][t] = aR[q].w;
            }
            if (t < 128) *(float4*)&Ws[nb][bk0][bc4*4] = bR;
        }
        __syncthreads();
        buf ^= 1;
    }

    float4 s0 = *(const float4*)&avs[tx*4];
    float4 d0 = *(const float4*)&avd[tx*4];
    float as[4] = {s0.x,s0.y,s0.z,s0.w};
    float ad[4] = {d0.x,d0.y,d0.z,d0.w};

#pragma unroll
    for (int i = 0; i < 8; i++) {
        int gr = r0 + ty*8 + i;
        if (gr >= Nrows) break;
        *(float4*)&g_h2[(size_t)gr*32 + tx*4] = make_float4(acc[i][0],acc[i][1],acc[i][2],acc[i][3]);
        float ps = 0.f, pd = 0.f;
#pragma unroll
        for (int j = 0; j < 4; j++) { ps = fmaf(acc[i][j], as[j], ps); pd = fmaf(acc[i][j], ad[j], pd); }
        ps += __shfl_xor_sync(0xffffffffu, ps, 1);
        pd += __shfl_xor_sync(0xffffffffu, pd, 1);
        ps += __shfl_xor_sync(0xffffffffu, ps, 2);
        pd += __shfl_xor_sync(0xffffffffu, pd, 2);
        ps += __shfl_xor_sync(0xffffffffu, ps, 4);
        pd += __shfl_xor_sync(0xffffffffu, pd, 4);
        if (tx == 0) { g_as2[gr] = ps; g_ad2[gr] = pd; }
    }
}

// ---------------- GAT1 gather: warp per dst node ----------------------------
__global__ __launch_bounds__(256) void k_gat1(
    const float* __restrict__ b1,
    const float* __restrict__ bg, const float* __restrict__ bb,
    const float* __restrict__ bm, const float* __restrict__ bv, int N)
{
    __shared__ float ws[8][32][4];
    int wid  = threadIdx.x >> 5;
    int lane = threadIdx.x & 31;
    int d    = blockIdx.x * 8 + wid;
    if (d >= N) return;
    int head = lane >> 3;

    float4 adv4 = *(const float4*)&g_ad1[d * 4];
    float advh  = head == 0 ? adv4.x : head == 1 ? adv4.y : head == 2 ? adv4.z : adv4.w;
    float4 asf  = *(const float4*)&g_as1[d * 4];
    float ash   = head == 0 ? asf.x : head == 1 ? asf.y : head == 2 ? asf.z : asf.w;

    float wself = __expf(lrelu(ash + advh));
    float4 hv = *(const float4*)&g_h1[(size_t)d * 128 + lane * 4];
    float4 acc = make_float4(wself*hv.x, wself*hv.y, wself*hv.z, wself*hv.w);
    float wsum = wself;

    int deg = min(g_deg[d], CAP);
    const int* lst = &g_csr[d * CAP];
    for (int j0 = 0; j0 < deg; j0 += 32) {
        int m = min(32, deg - j0);
        int sid = (lane < m) ? lst[j0 + lane] : 0;
        if (lane < m) {
            float4 a4 = __ldg((const float4*)&g_as1[sid * 4]);
            float4 w4;
            w4.x = __expf(lrelu(a4.x + adv4.x));
            w4.y = __expf(lrelu(a4.y + adv4.y));
            w4.z = __expf(lrelu(a4.z + adv4.z));
            w4.w = __expf(lrelu(a4.w + adv4.w));
            *(float4*)&ws[wid][lane][0] = w4;
        }
        __syncwarp();
#pragma unroll 4
        for (int jj = 0; jj < m; jj++) {
            int s = __shfl_sync(0xffffffffu, sid, jj);
            float w = ws[wid][jj][head];
            float4 h = *(const float4*)&g_h1[(size_t)s * 128 + lane * 4];
            acc.x = fmaf(w, h.x, acc.x);
            acc.y = fmaf(w, h.y, acc.y);
            acc.z = fmaf(w, h.z, acc.z);
            acc.w = fmaf(w, h.w, acc.w);
            wsum += w;
        }
        __syncwarp();
    }

    float inv = 1.f / wsum;
    float4 bc = *(const float4*)&b1[lane * 4];
    float4 g4 = *(const float4*)&bg[lane * 4];
    float4 b4 = *(const float4*)&bb[lane * 4];
    float4 m4 = *(const float4*)&bm[lane * 4];
    float4 v4 = *(const float4*)&bv[lane * 4];
    float4 o;
    o.x = (acc.x * inv + bc.x - m4.x) * rsqrtf(v4.x + BN_EPS) * g4.x + b4.x;
    o.y = (acc.y * inv + bc.y - m4.y) * rsqrtf(v4.y + BN_EPS) * g4.y + b4.y;
    o.z = (acc.z * inv + bc.z - m4.z) * rsqrtf(v4.z + BN_EPS) * g4.z + b4.z;
    o.w = (acc.w * inv + bc.w - m4.w) * rsqrtf(v4.w + BN_EPS) * g4.w + b4.w;
    o.x = o.x > 0.f ? o.x : expm1f(o.x);
    o.y = o.y > 0.f ? o.y : expm1f(o.y);
    o.z = o.z > 0.f ? o.z : expm1f(o.z);
    o.w = o.w > 0.f ? o.w : expm1f(o.w);
    *(float4*)&g_h1p[(size_t)d * 128 + lane * 4] = o;
}

// ---------------- GAT2 gather: warp per dst node (C=32, 1 head) -------------
__global__ __launch_bounds__(256) void k_gat2(const float* __restrict__ b2, int N) {
    int gw   = (blockIdx.x * blockDim.x + threadIdx.x) >> 5;
    int lane = threadIdx.x & 31;
    if (gw >= N) return;
    int d = gw;

    float adv = __ldg(&g_ad2[d]);
    float w = __expf(lrelu(__ldg(&g_as2[d]) + adv));
    float acc = w * g_h2[(size_t)d * 32 + lane];
    float wsum = w;

    int deg = min(g_deg[d], CAP);
    const int* lst = &g_csr[d * CAP];
    for (int j0 = 0; j0 < deg; j0 += 32) {
        int m = min(32, deg - j0);
        int sid = (lane < m) ? lst[j0 + lane] : 0;
        float wl = (lane < m) ? __expf(lrelu(__ldg(&g_as2[sid]) + adv)) : 0.f;
#pragma unroll 4
        for (int jj = 0; jj < m; jj++) {
            int s  = __shfl_sync(0xffffffffu, sid, jj);
            float we = __shfl_sync(0xffffffffu, wl, jj);
            acc = fmaf(we, __ldg(&g_h2[(size_t)s * 32 + lane]), acc);
            wsum += we;
        }
    }
    g_o2[(size_t)d * 32 + lane] = acc / wsum + __ldg(&b2[lane]);
    if (lane == 0) g_deg[d] = 0;
}

// ---------------- final: per-node MLP tail + log_softmax --------------------
__global__ void k_final(const float* __restrict__ ctx,
                        const float* __restrict__ rw1, const float* __restrict__ rb1,
                        const float* __restrict__ rw2, const float* __restrict__ rb2,
                        const float* __restrict__ dw,  const float* __restrict__ db,
                        const float* __restrict__ cw,  const float* __restrict__ cb,
                        float* __restrict__ out, int N) {
    __shared__ float sw[2666];
    int t = threadIdx.x;
    for (int i = t; i < 192;  i += 256) sw[i]        = rw1[i];
    for (int i = t; i < 32;   i += 256) sw[192 + i]  = rb1[i];
    for (int i = t; i < 1024; i += 256) sw[224 + i]  = rw2[i];
    for (int i = t; i < 32;   i += 256) sw[1248 + i] = rb2[i];
    for (int i = t; i < 1024; i += 256) sw[1280 + i] = dw[i];
    for (int i = t; i < 32;   i += 256) sw[2304 + i] = db[i];
    for (int i = t; i < 320;  i += 256) sw[2336 + i] = cw[i];
    for (int i = t; i < 10;   i += 256) sw[2656 + i] = cb[i];
    __syncthreads();

    int n = blockIdx.x * 256 + t;
    if (n >= N) return;

    float c0 = ctx[n * 6 + 0], c1 = ctx[n * 6 + 1], c2 = ctx[n * 6 + 2];
    float c3 = ctx[n * 6 + 3], c4 = ctx[n * 6 + 4], c5 = ctx[n * 6 + 5];

    float t1[32];
#pragma unroll
    for (int j = 0; j < 32; j++) {
        float v = sw[192 + j];
        v = fmaf(c0, sw[0 * 32 + j], v);
        v = fmaf(c1, sw[1 * 32 + j], v);
        v = fmaf(c2, sw[2 * 32 + j], v);
        v = fmaf(c3, sw[3 * 32 + j], v);
        v = fmaf(c4, sw[4 * 32 + j], v);
        v = fmaf(c5, sw[5 * 32 + j], v);
        t1[j] = fmaxf(v, 0.f);
    }
    float ex[32];
#pragma unroll
    for (int j = 0; j < 32; j++) {
        float v = sw[1248 + j];
#pragma unroll
        for (int k = 0; k < 32; k++) v = fmaf(t1[k], sw[224 + k * 32 + j], v);
        ex[j] = v;
    }
    float comb[32];
#pragma unroll
    for (int j = 0; j < 32; j++) {
        float rec = sw[2304 + j];
#pragma unroll
        for (int k = 0; k < 32; k++) rec = fmaf(ex[k], sw[1280 + k * 32 + j], rec);
        comb[j] = g_o2[(size_t)n * 32 + j] + RECON_W * rec;
    }
    float lg[10];
#pragma unroll
    for (int c = 0; c < 10; c++) {
        float v = sw[2656 + c];
#pragma unroll
        for (int j = 0; j < 32; j++) v = fmaf(comb[j], sw[2336 + j * 10 + c], v);
        lg[c] = v;
    }
    float m = lg[0];
#pragma unroll
    for (int c = 1; c < 10; c++) m = fmaxf(m, lg[c]);
    float sum = 0.f;
#pragma unroll
    for (int c = 0; c < 10; c++) sum += expf(lg[c] - m);
    float lse = m + logf(sum);
#pragma unroll
    for (int c = 0; c < 10; c++) out[n * 10 + c] = lg[c] - lse;
#pragma unroll
    for (int j = 0; j < 32; j++) out[N * 10 + n * 32 + j] = ex[j];
}

// ---------------- launch -----------------------------------------------------
extern "C" void kernel_launch(void* const* d_in, const int* in_sizes, int n_in,
                              void* d_out, int out_size) {
    const float* x    = (const float*)d_in[0];
    const int*   ei   = (const int*)  d_in[1];
    const float* ctx  = (const float*)d_in[2];
    const float* W1   = (const float*)d_in[3];
    const float* as1  = (const float*)d_in[4];
    const float* ad1  = (const float*)d_in[5];
    const float* b1   = (const float*)d_in[6];
    const float* bng  = (const float*)d_in[7];
    const float* bnb  = (const float*)d_in[8];
    const float* bnm  = (const float*)d_in[9];
    const float* bnv  = (const float*)d_in[10];
    const float* W2   = (const float*)d_in[11];
    const float* as2  = (const float*)d_in[12];
    const float* ad2  = (const float*)d_in[13];
    const float* b2   = (const float*)d_in[14];
    const float* rw1  = (const float*)d_in[15];
    const float* rb1  = (const float*)d_in[16];
    const float* rw2  = (const float*)d_in[17];
    const float* rb2  = (const float*)d_in[18];
    const float* dw   = (const float*)d_in[19];
    const float* db   = (const float*)d_in[20];
    const float* cw   = (const float*)d_in[21];
    const float* cb   = (const float*)d_in[22];
    float* out = (float*)d_out;

    int N = in_sizes[0] / 128;
    int E = in_sizes[1] / 2;

    static bool attr_set = false;
    if (!attr_set) {
        cudaFuncSetAttribute(k_gemm1_hmma, cudaFuncAttributeMaxDynamicSharedMemorySize, SM_TOT);
        attr_set = true;
    }

    // adjacency build (g_deg starts/stays zeroed; reset by k_gat2)
    k_fill<<<(E + 255) / 256, 256>>>(ei, E);
    k_prep_w1<<<64, 256>>>(W1);

    // layer 1: HMMA GEMM + fused alpha, then gather
    k_gemm1_hmma<<<(N + 127) / 128, 256, SM_TOT>>>(x, as1, ad1, N);
    k_gat1<<<(N + 7) / 8, 256>>>(b1, bng, bnb, bnm, bnv, N);

    // layer 2
    k_gemm2<<<(N + 255) / 256, 256>>>(W2, as2, ad2, N);
    k_gat2<<<(N * 32 + 255) / 256, 256>>>(b2, N);

    k_final<<<(N + 255) / 256, 256>>>(ctx, rw1, rb1, rw2, rb2, dw, db, cw, cb,
                                      out, N);
}

// round 7
// speedup vs baseline: 1.2380x; 1.1325x over previous
#include <cuda_runtime.h>
#include <cuda_bf16.h>
#include <math.h>

#define MAXN 100000
#define CAP  128
#define NEG_SLOPE 0.2f
#define BN_EPS 1e-5f
#define RECON_W 0.1f

// ---------------- scratch (device globals) ----------------------------------
__device__ float g_h1 [MAXN * 128];   // x @ W1
__device__ float g_h1p[MAXN * 128];   // after GAT1 + BN + ELU
__device__ float g_h2 [MAXN * 32];    // h1p @ W2
__device__ float g_o2 [MAXN * 32];    // after GAT2 + bias
__device__ float g_as1[MAXN * 4];
__device__ float g_ad1[MAXN * 4];
__device__ float g_as2[MAXN];
__device__ float g_ad2[MAXN];
__device__ int   g_deg[MAXN];         // zeroed invariant: reset by k_gat2
__device__ int   g_csr[MAXN * CAP];   // per-dst src lists (bucketed)
__device__ __nv_bfloat16 g_w1hi[128 * 136];  // W1^T bf16 hi, n-major padded
__device__ __nv_bfloat16 g_w1lo[128 * 136];  // W1^T bf16 lo, n-major padded

__device__ __forceinline__ float lrelu(float t) { return t > 0.f ? t : NEG_SLOPE * t; }

__device__ __forceinline__ unsigned s2u(const void* p) {
    unsigned a;
    asm("{ .reg .u64 t; cvta.to.shared.u64 t, %1; cvt.u32.u64 %0, t; }" : "=r"(a) : "l"(p));
    return a;
}

#define LDSM4(f, addr) \
    asm volatile("ldmatrix.sync.aligned.m8n8.x4.shared.b16 {%0,%1,%2,%3}, [%4];" \
        : "=r"((f)[0]),"=r"((f)[1]),"=r"((f)[2]),"=r"((f)[3]) : "r"(addr))

#define MMA_BF16(dd, a, b0, b1) \
    asm volatile("mma.sync.aligned.m16n8k16.row.col.f32.bf16.bf16.f32 " \
        "{%0,%1,%2,%3}, {%4,%5,%6,%7}, {%8,%9}, {%0,%1,%2,%3};" \
        : "+f"((dd)[0]),"+f"((dd)[1]),"+f"((dd)[2]),"+f"((dd)[3]) \
        : "r"((a)[0]),"r"((a)[1]),"r"((a)[2]),"r"((a)[3]), "r"(b0),"r"(b1))

// ---------------- fused adjacency build + W1 prep ----------------------------
__global__ void k_fill_prep(const int* __restrict__ ei, const float* __restrict__ W1, int E) {
    int b = blockIdx.x;
    if (b < 64) {
        int i = b * 256 + threadIdx.x;   // i = k*128 + n
        int k = i >> 7, n = i & 127;
        float v = W1[i];
        __nv_bfloat16 hi = __float2bfloat16(v);
        __nv_bfloat16 lo = __float2bfloat16(v - __bfloat162float(hi));
        g_w1hi[n * 136 + k] = hi;
        g_w1lo[n * 136 + k] = lo;
        return;
    }
    int e = (b - 64) * 256 + threadIdx.x;
    if (e >= E) return;
    int s = ei[e], d = ei[E + e];
    int pos = atomicAdd(&g_deg[d], 1);
    if (pos < CAP) g_csr[d * CAP + pos] = s;
}

// ============================================================================
// GEMM1 via mma.sync bf16 (3-chain hi/lo): g_h1[N,128] = x[N,128] @ W1[128,128]
// + fused alpha1 epilogue. Split-K staging: 2 phases of 64 K-cols, smem 74KB
// -> 2 CTAs/SM. 256 threads, 128 rows/CTA.
// ============================================================================
#define SMH_ELE (128 * 72)
#define SM_TOT  (4 * SMH_ELE * 2 + 1024)

__global__ __launch_bounds__(256) void k_gemm1_hmma(
    const float* __restrict__ x,
    const float* __restrict__ avs, const float* __restrict__ avd, int N)
{
    extern __shared__ char sm[];
    __nv_bfloat16* Ahi = (__nv_bfloat16*)sm;
    __nv_bfloat16* Alo = Ahi + SMH_ELE;
    __nv_bfloat16* Whi = Alo + SMH_ELE;
    __nv_bfloat16* Wlo = Whi + SMH_ELE;
    float* s_as = (float*)(Wlo + SMH_ELE);
    float* s_ad = s_as + 128;

    int t = threadIdx.x;
    int r0 = blockIdx.x * 128;
    int wid = t >> 5, lane = t & 31;
    int j = lane >> 3, rin = lane & 7;

    if (t < 128) { s_as[t] = avs[t]; s_ad[t] = avd[t]; }

    int arow = t >> 1, ac0 = (t & 1) * 32;
    int gr_s = r0 + arow;
    bool aval = gr_s < N;
    int wn = t >> 1, wk0 = (t & 1) * 32;

    unsigned aOff = ((unsigned)((wid * 16 + (j & 1) * 8 + rin) * 72 + (j >> 1) * 8)) * 2;
    unsigned bOff = ((unsigned)(((j >> 1) * 8 + rin) * 72 + (j & 1) * 8)) * 2;
    unsigned aHiB = s2u(Ahi) + aOff, aLoB = s2u(Alo) + aOff;
    unsigned wHiB = s2u(Whi) + bOff, wLoB = s2u(Wlo) + bOff;

    float d[16][4];
#pragma unroll
    for (int i = 0; i < 16; i++)
#pragma unroll
        for (int q = 0; q < 4; q++) d[i][q] = 0.f;

#pragma unroll 1
    for (int half = 0; half < 2; half++) {
        if (half) __syncthreads();
        // stage A half: rows 0..127, global cols half*64+ac0 .. +32
        {
            const float* xr = x + (size_t)gr_s * 128 + half * 64 + ac0;
#pragma unroll
            for (int c = 0; c < 32; c += 4) {
                float4 v = aval ? *(const float4*)(xr + c) : make_float4(0, 0, 0, 0);
                float f[4] = {v.x, v.y, v.z, v.w};
                __nv_bfloat16 h[4], l[4];
#pragma unroll
                for (int q = 0; q < 4; q++) {
                    h[q] = __float2bfloat16(f[q]);
                    l[q] = __float2bfloat16(f[q] - __bfloat162float(h[q]));
                }
                int eo = arow * 72 + ac0 + c;
                *(__nv_bfloat162*)&Ahi[eo]     = __nv_bfloat162(h[0], h[1]);
                *(__nv_bfloat162*)&Ahi[eo + 2] = __nv_bfloat162(h[2], h[3]);
                *(__nv_bfloat162*)&Alo[eo]     = __nv_bfloat162(l[0], l[1]);
                *(__nv_bfloat162*)&Alo[eo + 2] = __nv_bfloat162(l[2], l[3]);
            }
        }
        // stage W half
        {
#pragma unroll
            for (int q = 0; q < 4; q++) {
                int so = wn * 136 + half * 64 + wk0 + q * 8;
                int doff = wn * 72 + wk0 + q * 8;
                *(float4*)&Whi[doff] = *(const float4*)&g_w1hi[so];
                *(float4*)&Wlo[doff] = *(const float4*)&g_w1lo[so];
            }
        }
        __syncthreads();

#pragma unroll
        for (int ks = 0; ks < 4; ks++) {
            unsigned ah[4], al[4];
            LDSM4(ah, aHiB + ks * 32);
            LDSM4(al, aLoB + ks * 32);
#pragma unroll
            for (int p = 0; p < 8; p++) {
                unsigned bh[4], bl[4];
                LDSM4(bh, wHiB + p * 2304 + ks * 32);
                LDSM4(bl, wLoB + p * 2304 + ks * 32);
                MMA_BF16(d[2*p],     ah, bh[0], bh[1]);
                MMA_BF16(d[2*p + 1], ah, bh[2], bh[3]);
                MMA_BF16(d[2*p],     al, bh[0], bh[1]);
                MMA_BF16(d[2*p + 1], al, bh[2], bh[3]);
                MMA_BF16(d[2*p],     ah, bl[0], bl[1]);
                MMA_BF16(d[2*p + 1], ah, bl[2], bl[3]);
            }
        }
    }

    // epilogue: write h1 + fused alpha1 (rows rA = g, rB = g+8 of this warp)
    int g = lane >> 2, t4 = lane & 3;
    int rA = r0 + wid * 16 + g, rB = rA + 8;
    float psA[4] = {0,0,0,0}, pdA[4] = {0,0,0,0};
    float psB[4] = {0,0,0,0}, pdB[4] = {0,0,0,0};
#pragma unroll
    for (int nt = 0; nt < 16; nt++) {
        int n0 = nt * 8 + 2 * t4;
        float w0s = s_as[n0], w1s = s_as[n0 + 1];
        float w0d = s_ad[n0], w1d = s_ad[n0 + 1];
        int h = nt >> 2;
        psA[h] = fmaf(d[nt][0], w0s, fmaf(d[nt][1], w1s, psA[h]));
        pdA[h] = fmaf(d[nt][0], w0d, fmaf(d[nt][1], w1d, pdA[h]));
        psB[h] = fmaf(d[nt][2], w0s, fmaf(d[nt][3], w1s, psB[h]));
        pdB[h] = fmaf(d[nt][2], w0d, fmaf(d[nt][3], w1d, pdB[h]));
        if (rA < N) *(float2*)&g_h1[(size_t)rA * 128 + n0] = make_float2(d[nt][0], d[nt][1]);
        if (rB < N) *(float2*)&g_h1[(size_t)rB * 128 + n0] = make_float2(d[nt][2], d[nt][3]);
    }
#pragma unroll
    for (int h = 0; h < 4; h++) {
        psA[h] += __shfl_xor_sync(0xffffffffu, psA[h], 1);
        pdA[h] += __shfl_xor_sync(0xffffffffu, pdA[h], 1);
        psB[h] += __shfl_xor_sync(0xffffffffu, psB[h], 1);
        pdB[h] += __shfl_xor_sync(0xffffffffu, pdB[h], 1);
        psA[h] += __shfl_xor_sync(0xffffffffu, psA[h], 2);
        pdA[h] += __shfl_xor_sync(0xffffffffu, pdA[h], 2);
        psB[h] += __shfl_xor_sync(0xffffffffu, psB[h], 2);
        pdB[h] += __shfl_xor_sync(0xffffffffu, pdB[h], 2);
    }
    if (t4 == 0) {
        if (rA < N) {
#pragma unroll
            for (int h = 0; h < 4; h++) { g_as1[rA*4 + h] = psA[h]; g_ad1[rA*4 + h] = pdA[h]; }
        }
        if (rB < N) {
#pragma unroll
            for (int h = 0; h < 4; h++) { g_as1[rB*4 + h] = psB[h]; g_ad1[rB*4 + h] = pdB[h]; }
        }
    }
}

// ============================================================================
// GEMM2: g_h2[N,32] = g_h1p[N,128] @ W2[128,32], fused alpha2 epilogue.
// ============================================================================
__global__ __launch_bounds__(256) void k_gemm2(
    const float* __restrict__ B,
    const float* __restrict__ avs, const float* __restrict__ avd, int Nrows)
{
    __shared__ float Xs[2][16][256];
    __shared__ float Ws[2][16][32];
    const float* A = g_h1p;
    int t  = threadIdx.x;
    int tx = t & 7, ty = t >> 3;
    int r0 = blockIdx.x * 256;

    bool aval = (r0 + t) < Nrows;
    const float* Abase = A + (size_t)(r0 + t) * 128;
    int bk0 = t >> 3, bc4 = t & 7;

    {
#pragma unroll
        for (int q = 0; q < 4; q++) {
            float4 v = aval ? *(const float4*)(Abase + q*4) : make_float4(0,0,0,0);
            Xs[0][q*4+0][t] = v.x; Xs[0][q*4+1][t] = v.y;
            Xs[0][q*4+2][t] = v.z; Xs[0][q*4+3][t] = v.w;
        }
        if (t < 128) *(float4*)&Ws[0][bk0][bc4*4] = *(const float4*)&B[bk0*32 + bc4*4];
    }
    __syncthreads();

    float acc[8][4];
#pragma unroll
    for (int i = 0; i < 8; i++)
#pragma unroll
        for (int j = 0; j < 4; j++) acc[i][j] = 0.f;

    int buf = 0;
    for (int kb = 0; kb < 128; kb += 16) {
        bool has_next = (kb + 16) < 128;
        float4 aR[4]; float4 bR;
        if (has_next) {
#pragma unroll
            for (int q = 0; q < 4; q++)
                aR[q] = aval ? *(const float4*)(Abase + kb + 16 + q*4) : make_float4(0,0,0,0);
            if (t < 128) bR = *(const float4*)&B[(kb + 16 + bk0)*32 + bc4*4];
        }
#pragma unroll
        for (int kk = 0; kk < 16; kk++) {
            float4 a0 = *(const float4*)&Xs[buf][kk][ty*8];
            float4 a1 = *(const float4*)&Xs[buf][kk][ty*8 + 4];
            float4 b0 = *(const float4*)&Ws[buf][kk][tx*4];
            float av[8] = {a0.x,a0.y,a0.z,a0.w,a1.x,a1.y,a1.z,a1.w};
            float bv[4] = {b0.x,b0.y,b0.z,b0.w};
#pragma unroll
            for (int i = 0; i < 8; i++)
#pragma unroll
                for (int j = 0; j < 4; j++) acc[i][j] = fmaf(av[i], bv[j], acc[i][j]);
        }
        if (has_next) {
            int nb = buf ^ 1;
#pragma unroll
            for (int q = 0; q < 4; q++) {
                Xs[nb][q*4+0][t] = aR[q].x; Xs[nb][q*4+1][t] = aR[q].y;
                Xs[nb][q*4+2][t] = aR[q].z; Xs[nb][q*4+3][t] = aR[q].w;
            }
            if (t < 128) *(float4*)&Ws[nb][bk0][bc4*4] = bR;
        }
        __syncthreads();
        buf ^= 1;
    }

    float4 s0 = *(const float4*)&avs[tx*4];
    float4 d0 = *(const float4*)&avd[tx*4];
    float as[4] = {s0.x,s0.y,s0.z,s0.w};
    float ad[4] = {d0.x,d0.y,d0.z,d0.w};

#pragma unroll
    for (int i = 0; i < 8; i++) {
        int gr = r0 + ty*8 + i;
        if (gr >= Nrows) break;
        *(float4*)&g_h2[(size_t)gr*32 + tx*4] = make_float4(acc[i][0],acc[i][1],acc[i][2],acc[i][3]);
        float ps = 0.f, pd = 0.f;
#pragma unroll
        for (int j = 0; j < 4; j++) { ps = fmaf(acc[i][j], as[j], ps); pd = fmaf(acc[i][j], ad[j], pd); }
        ps += __shfl_xor_sync(0xffffffffu, ps, 1);
        pd += __shfl_xor_sync(0xffffffffu, pd, 1);
        ps += __shfl_xor_sync(0xffffffffu, ps, 2);
        pd += __shfl_xor_sync(0xffffffffu, pd, 2);
        ps += __shfl_xor_sync(0xffffffffu, ps, 4);
        pd += __shfl_xor_sync(0xffffffffu, pd, 4);
        if (tx == 0) { g_as2[gr] = ps; g_ad2[gr] = pd; }
    }
}

// ---------------- GAT1 gather: warp per dst node (round-3 form) -------------
__global__ __launch_bounds__(256) void k_gat1(
    const float* __restrict__ b1,
    const float* __restrict__ bg, const float* __restrict__ bb,
    const float* __restrict__ bm, const float* __restrict__ bv, int N)
{
    int gw   = (blockIdx.x * blockDim.x + threadIdx.x) >> 5;
    int lane = threadIdx.x & 31;
    if (gw >= N) return;
    int d    = gw;
    int head = lane >> 3;

    float adv = __ldg(&g_ad1[d * 4 + head]);

    float wself = __expf(lrelu(__ldg(&g_as1[d * 4 + head]) + adv));
    float4 hv = *(const float4*)&g_h1[(size_t)d * 128 + lane * 4];
    float4 acc = make_float4(wself*hv.x, wself*hv.y, wself*hv.z, wself*hv.w);
    float wsum = wself;

    int deg = min(g_deg[d], CAP);
    const int* lst = &g_csr[d * CAP];
    for (int j0 = 0; j0 < deg; j0 += 32) {
        int sid = (j0 + lane < deg) ? lst[j0 + lane] : 0;
        int m = min(32, deg - j0);
#pragma unroll 4
        for (int jj = 0; jj < m; jj++) {
            int s = __shfl_sync(0xffffffffu, sid, jj);
            float we = __expf(lrelu(__ldg(&g_as1[s * 4 + head]) + adv));
            float4 h = *(const float4*)&g_h1[(size_t)s * 128 + lane * 4];
            acc.x = fmaf(we, h.x, acc.x);
            acc.y = fmaf(we, h.y, acc.y);
            acc.z = fmaf(we, h.z, acc.z);
            acc.w = fmaf(we, h.w, acc.w);
            wsum += we;
        }
    }

    float inv = 1.f / wsum;
    float4 bc = *(const float4*)&b1[lane * 4];
    float4 g4 = *(const float4*)&bg[lane * 4];
    float4 b4 = *(const float4*)&bb[lane * 4];
    float4 m4 = *(const float4*)&bm[lane * 4];
    float4 v4 = *(const float4*)&bv[lane * 4];
    float4 o;
    o.x = (acc.x * inv + bc.x - m4.x) * rsqrtf(v4.x + BN_EPS) * g4.x + b4.x;
    o.y = (acc.y * inv + bc.y - m4.y) * rsqrtf(v4.y + BN_EPS) * g4.y + b4.y;
    o.z = (acc.z * inv + bc.z - m4.z) * rsqrtf(v4.z + BN_EPS) * g4.z + b4.z;
    o.w = (acc.w * inv + bc.w - m4.w) * rsqrtf(v4.w + BN_EPS) * g4.w + b4.w;
    o.x = o.x > 0.f ? o.x : expm1f(o.x);
    o.y = o.y > 0.f ? o.y : expm1f(o.y);
    o.z = o.z > 0.f ? o.z : expm1f(o.z);
    o.w = o.w > 0.f ? o.w : expm1f(o.w);
    *(float4*)&g_h1p[(size_t)d * 128 + lane * 4] = o;
}

// ---------------- GAT2 gather: warp per dst node (C=32, 1 head) -------------
__global__ __launch_bounds__(256) void k_gat2(const float* __restrict__ b2, int N) {
    int gw   = (blockIdx.x * blockDim.x + threadIdx.x) >> 5;
    int lane = threadIdx.x & 31;
    if (gw >= N) return;
    int d = gw;

    float adv = __ldg(&g_ad2[d]);
    float w = __expf(lrelu(__ldg(&g_as2[d]) + adv));
    float acc = w * g_h2[(size_t)d * 32 + lane];
    float wsum = w;

    int deg = min(g_deg[d], CAP);
    const int* lst = &g_csr[d * CAP];
    for (int j0 = 0; j0 < deg; j0 += 32) {
        int m = min(32, deg - j0);
        int sid = (lane < m) ? lst[j0 + lane] : 0;
        float wl = (lane < m) ? __expf(lrelu(__ldg(&g_as2[sid]) + adv)) : 0.f;
#pragma unroll 4
        for (int jj = 0; jj < m; jj++) {
            int s  = __shfl_sync(0xffffffffu, sid, jj);
            float we = __shfl_sync(0xffffffffu, wl, jj);
            acc = fmaf(we, __ldg(&g_h2[(size_t)s * 32 + lane]), acc);
            wsum += we;
        }
    }
    g_o2[(size_t)d * 32 + lane] = acc / wsum + __ldg(&b2[lane]);
    if (lane == 0) g_deg[d] = 0;
}

// ---------------- final: per-node MLP tail + log_softmax --------------------
__global__ void k_final(const float* __restrict__ ctx,
                        const float* __restrict__ rw1, const float* __restrict__ rb1,
                        const float* __restrict__ rw2, const float* __restrict__ rb2,
                        const float* __restrict__ dw,  const float* __restrict__ db,
                        const float* __restrict__ cw,  const float* __restrict__ cb,
                        float* __restrict__ out, int N) {
    __shared__ float sw[2666];
    int t = threadIdx.x;
    for (int i = t; i < 192;  i += 256) sw[i]        = rw1[i];
    for (int i = t; i < 32;   i += 256) sw[192 + i]  = rb1[i];
    for (int i = t; i < 1024; i += 256) sw[224 + i]  = rw2[i];
    for (int i = t; i < 32;   i += 256) sw[1248 + i] = rb2[i];
    for (int i = t; i < 1024; i += 256) sw[1280 + i] = dw[i];
    for (int i = t; i < 32;   i += 256) sw[2304 + i] = db[i];
    for (int i = t; i < 320;  i += 256) sw[2336 + i] = cw[i];
    for (int i = t; i < 10;   i += 256) sw[2656 + i] = cb[i];
    __syncthreads();

    int n = blockIdx.x * 256 + t;
    if (n >= N) return;

    float c0 = ctx[n * 6 + 0], c1 = ctx[n * 6 + 1], c2 = ctx[n * 6 + 2];
    float c3 = ctx[n * 6 + 3], c4 = ctx[n * 6 + 4], c5 = ctx[n * 6 + 5];

    float t1[32];
#pragma unroll
    for (int j = 0; j < 32; j++) {
        float v = sw[192 + j];
        v = fmaf(c0, sw[0 * 32 + j], v);
        v = fmaf(c1, sw[1 * 32 + j], v);
        v = fmaf(c2, sw[2 * 32 + j], v);
        v = fmaf(c3, sw[3 * 32 + j], v);
        v = fmaf(c4, sw[4 * 32 + j], v);
        v = fmaf(c5, sw[5 * 32 + j], v);
        t1[j] = fmaxf(v, 0.f);
    }
    float ex[32];
#pragma unroll
    for (int j = 0; j < 32; j++) {
        float v = sw[1248 + j];
#pragma unroll
        for (int k = 0; k < 32; k++) v = fmaf(t1[k], sw[224 + k * 32 + j], v);
        ex[j] = v;
    }
    float comb[32];
#pragma unroll
    for (int j = 0; j < 32; j++) {
        float rec = sw[2304 + j];
#pragma unroll
        for (int k = 0; k < 32; k++) rec = fmaf(ex[k], sw[1280 + k * 32 + j], rec);
        comb[j] = g_o2[(size_t)n * 32 + j] + RECON_W * rec;
    }
    float lg[10];
#pragma unroll
    for (int c = 0; c < 10; c++) {
        float v = sw[2656 + c];
#pragma unroll
        for (int j = 0; j < 32; j++) v = fmaf(comb[j], sw[2336 + j * 10 + c], v);
        lg[c] = v;
    }
    float m = lg[0];
#pragma unroll
    for (int c = 1; c < 10; c++) m = fmaxf(m, lg[c]);
    float sum = 0.f;
#pragma unroll
    for (int c = 0; c < 10; c++) sum += expf(lg[c] - m);
    float lse = m + logf(sum);
#pragma unroll
    for (int c = 0; c < 10; c++) out[n * 10 + c] = lg[c] - lse;
#pragma unroll
    for (int j = 0; j < 32; j++) out[N * 10 + n * 32 + j] = ex[j];
}

// ---------------- launch -----------------------------------------------------
extern "C" void kernel_launch(void* const* d_in, const int* in_sizes, int n_in,
                              void* d_out, int out_size) {
    const float* x    = (const float*)d_in[0];
    const int*   ei   = (const int*)  d_in[1];
    const float* ctx  = (const float*)d_in[2];
    const float* W1   = (const float*)d_in[3];
    const float* as1  = (const float*)d_in[4];
    const float* ad1  = (const float*)d_in[5];
    const float* b1   = (const float*)d_in[6];
    const float* bng  = (const float*)d_in[7];
    const float* bnb  = (const float*)d_in[8];
    const float* bnm  = (const float*)d_in[9];
    const float* bnv  = (const float*)d_in[10];
    const float* W2   = (const float*)d_in[11];
    const float* as2  = (const float*)d_in[12];
    const float* ad2  = (const float*)d_in[13];
    const float* b2   = (const float*)d_in[14];
    const float* rw1  = (const float*)d_in[15];
    const float* rb1  = (const float*)d_in[16];
    const float* rw2  = (const float*)d_in[17];
    const float* rb2  = (const float*)d_in[18];
    const float* dw   = (const float*)d_in[19];
    const float* db   = (const float*)d_in[20];
    const float* cw   = (const float*)d_in[21];
    const float* cb   = (const float*)d_in[22];
    float* out = (float*)d_out;

    int N = in_sizes[0] / 128;
    int E = in_sizes[1] / 2;

    static bool attr_set = false;
    if (!attr_set) {
        cudaFuncSetAttribute(k_gemm1_hmma, cudaFuncAttributeMaxDynamicSharedMemorySize, SM_TOT);
        attr_set = true;
    }

    // fused adjacency build + W1 prep (g_deg starts/stays zeroed; reset by k_gat2)
    k_fill_prep<<<64 + (E + 255) / 256, 256>>>(ei, W1, E);

    // layer 1: HMMA GEMM + fused alpha, then gather
    k_gemm1_hmma<<<(N + 127) / 128, 256, SM_TOT>>>(x, as1, ad1, N);
    k_gat1<<<(N * 32 + 255) / 256, 256>>>(b1, bng, bnb, bnm, bnv, N);

    // layer 2
    k_gemm2<<<(N + 255) / 256, 256>>>(W2, as2, ad2, N);
    k_gat2<<<(N * 32 + 255) / 256, 256>>>(b2, N);

    k_final<<<(N + 255) / 256, 256>>>(ctx, rw1, rb1, rw2, rb2, dw, db, cw, cb,
                                      out, N);
}

// round 8
// speedup vs baseline: 1.2403x; 1.0018x over previous
#include <cuda_runtime.h>
#include <cuda_bf16.h>
#include <math.h>

#define MAXN 100000
#define CAP  128
#define NEG_SLOPE 0.2f
#define BN_EPS 1e-5f
#define RECON_W 0.1f

// ---------------- scratch (device globals) ----------------------------------
__device__ float g_h1 [MAXN * 128];   // x @ W1
__device__ float g_h1p[MAXN * 128];   // after GAT1 + BN + ELU
__device__ float g_h2 [MAXN * 32];    // h1p @ W2
__device__ float g_o2 [MAXN * 32];    // after GAT2 + bias
__device__ float g_as1[MAXN * 4];
__device__ float g_ad1[MAXN * 4];
__device__ float g_as2[MAXN];
__device__ float g_ad2[MAXN];
__device__ int   g_deg[MAXN];         // zeroed invariant: reset by k_gat2
__device__ int   g_csr[MAXN * CAP];   // per-dst src lists (bucketed)
__device__ __nv_bfloat16 g_w1hi[128 * 136];  // W1^T bf16 hi, n-major padded
__device__ __nv_bfloat16 g_w1lo[128 * 136];
__device__ __nv_bfloat16 g_w2hi[32 * 136];   // W2^T bf16 hi, n-major padded
__device__ __nv_bfloat16 g_w2lo[32 * 136];

__device__ __forceinline__ float lrelu(float t) { return t > 0.f ? t : NEG_SLOPE * t; }

__device__ __forceinline__ unsigned s2u(const void* p) {
    unsigned a;
    asm("{ .reg .u64 t; cvta.to.shared.u64 t, %1; cvt.u32.u64 %0, t; }" : "=r"(a) : "l"(p));
    return a;
}

#define LDSM4(f, addr) \
    asm volatile("ldmatrix.sync.aligned.m8n8.x4.shared.b16 {%0,%1,%2,%3}, [%4];" \
        : "=r"((f)[0]),"=r"((f)[1]),"=r"((f)[2]),"=r"((f)[3]) : "r"(addr))

#define MMA_BF16(dd, a, b0, b1) \
    asm volatile("mma.sync.aligned.m16n8k16.row.col.f32.bf16.bf16.f32 " \
        "{%0,%1,%2,%3}, {%4,%5,%6,%7}, {%8,%9}, {%0,%1,%2,%3};" \
        : "+f"((dd)[0]),"+f"((dd)[1]),"+f"((dd)[2]),"+f"((dd)[3]) \
        : "r"((a)[0]),"r"((a)[1]),"r"((a)[2]),"r"((a)[3]), "r"(b0),"r"(b1))

// ---------------- fused adjacency build + W1/W2 prep -------------------------
__global__ void k_fill_prep(const int* __restrict__ ei, const float* __restrict__ W1,
                            const float* __restrict__ W2, int E) {
    int b = blockIdx.x;
    if (b < 64) {                       // W1: [128,128] k-major -> [n][136]
        int i = b * 256 + threadIdx.x;
        int k = i >> 7, n = i & 127;
        float v = W1[i];
        __nv_bfloat16 hi = __float2bfloat16(v);
        __nv_bfloat16 lo = __float2bfloat16(v - __bfloat162float(hi));
        g_w1hi[n * 136 + k] = hi;
        g_w1lo[n * 136 + k] = lo;
        return;
    }
    if (b < 80) {                       // W2: [128,32] k-major -> [n][136]
        int i = (b - 64) * 256 + threadIdx.x;
        int k = i >> 5, n = i & 31;
        float v = W2[i];
        __nv_bfloat16 hi = __float2bfloat16(v);
        __nv_bfloat16 lo = __float2bfloat16(v - __bfloat162float(hi));
        g_w2hi[n * 136 + k] = hi;
        g_w2lo[n * 136 + k] = lo;
        return;
    }
    int e = (b - 80) * 256 + threadIdx.x;
    if (e >= E) return;
    int s = ei[e], d = ei[E + e];
    int pos = atomicAdd(&g_deg[d], 1);
    if (pos < CAP) g_csr[d * CAP + pos] = s;
}

// ============================================================================
// GEMM1 via mma.sync bf16 (3-chain hi/lo) + fused alpha1. Split-K, 2 phases.
// ============================================================================
#define SMH_ELE (128 * 72)
#define SM_TOT  (4 * SMH_ELE * 2 + 1024)

__global__ __launch_bounds__(256) void k_gemm1_hmma(
    const float* __restrict__ x,
    const float* __restrict__ avs, const float* __restrict__ avd, int N)
{
    extern __shared__ char sm[];
    __nv_bfloat16* Ahi = (__nv_bfloat16*)sm;
    __nv_bfloat16* Alo = Ahi + SMH_ELE;
    __nv_bfloat16* Whi = Alo + SMH_ELE;
    __nv_bfloat16* Wlo = Whi + SMH_ELE;
    float* s_as = (float*)(Wlo + SMH_ELE);
    float* s_ad = s_as + 128;

    int t = threadIdx.x;
    int r0 = blockIdx.x * 128;
    int wid = t >> 5, lane = t & 31;
    int j = lane >> 3, rin = lane & 7;

    if (t < 128) { s_as[t] = avs[t]; s_ad[t] = avd[t]; }

    int arow = t >> 1, ac0 = (t & 1) * 32;
    int gr_s = r0 + arow;
    bool aval = gr_s < N;
    int wn = t >> 1, wk0 = (t & 1) * 32;

    unsigned aOff = ((unsigned)((wid * 16 + (j & 1) * 8 + rin) * 72 + (j >> 1) * 8)) * 2;
    unsigned bOff = ((unsigned)(((j >> 1) * 8 + rin) * 72 + (j & 1) * 8)) * 2;
    unsigned aHiB = s2u(Ahi) + aOff, aLoB = s2u(Alo) + aOff;
    unsigned wHiB = s2u(Whi) + bOff, wLoB = s2u(Wlo) + bOff;

    float d[16][4];
#pragma unroll
    for (int i = 0; i < 16; i++)
#pragma unroll
        for (int q = 0; q < 4; q++) d[i][q] = 0.f;

#pragma unroll 1
    for (int half = 0; half < 2; half++) {
        if (half) __syncthreads();
        {
            const float* xr = x + (size_t)gr_s * 128 + half * 64 + ac0;
#pragma unroll
            for (int c = 0; c < 32; c += 4) {
                float4 v = aval ? *(const float4*)(xr + c) : make_float4(0, 0, 0, 0);
                float f[4] = {v.x, v.y, v.z, v.w};
                __nv_bfloat16 h[4], l[4];
#pragma unroll
                for (int q = 0; q < 4; q++) {
                    h[q] = __float2bfloat16(f[q]);
                    l[q] = __float2bfloat16(f[q] - __bfloat162float(h[q]));
                }
                int eo = arow * 72 + ac0 + c;
                *(__nv_bfloat162*)&Ahi[eo]     = __nv_bfloat162(h[0], h[1]);
                *(__nv_bfloat162*)&Ahi[eo + 2] = __nv_bfloat162(h[2], h[3]);
                *(__nv_bfloat162*)&Alo[eo]     = __nv_bfloat162(l[0], l[1]);
                *(__nv_bfloat162*)&Alo[eo + 2] = __nv_bfloat162(l[2], l[3]);
            }
        }
        {
#pragma unroll
            for (int q = 0; q < 4; q++) {
                int so = wn * 136 + half * 64 + wk0 + q * 8;
                int doff = wn * 72 + wk0 + q * 8;
                *(float4*)&Whi[doff] = *(const float4*)&g_w1hi[so];
                *(float4*)&Wlo[doff] = *(const float4*)&g_w1lo[so];
            }
        }
        __syncthreads();

#pragma unroll
        for (int ks = 0; ks < 4; ks++) {
            unsigned ah[4], al[4];
            LDSM4(ah, aHiB + ks * 32);
            LDSM4(al, aLoB + ks * 32);
#pragma unroll
            for (int p = 0; p < 8; p++) {
                unsigned bh[4], bl[4];
                LDSM4(bh, wHiB + p * 2304 + ks * 32);
                LDSM4(bl, wLoB + p * 2304 + ks * 32);
                MMA_BF16(d[2*p],     ah, bh[0], bh[1]);
                MMA_BF16(d[2*p + 1], ah, bh[2], bh[3]);
                MMA_BF16(d[2*p],     al, bh[0], bh[1]);
                MMA_BF16(d[2*p + 1], al, bh[2], bh[3]);
                MMA_BF16(d[2*p],     ah, bl[0], bl[1]);
                MMA_BF16(d[2*p + 1], ah, bl[2], bl[3]);
            }
        }
    }

    int g = lane >> 2, t4 = lane & 3;
    int rA = r0 + wid * 16 + g, rB = rA + 8;
    float psA[4] = {0,0,0,0}, pdA[4] = {0,0,0,0};
    float psB[4] = {0,0,0,0}, pdB[4] = {0,0,0,0};
#pragma unroll
    for (int nt = 0; nt < 16; nt++) {
        int n0 = nt * 8 + 2 * t4;
        float w0s = s_as[n0], w1s = s_as[n0 + 1];
        float w0d = s_ad[n0], w1d = s_ad[n0 + 1];
        int h = nt >> 2;
        psA[h] = fmaf(d[nt][0], w0s, fmaf(d[nt][1], w1s, psA[h]));
        pdA[h] = fmaf(d[nt][0], w0d, fmaf(d[nt][1], w1d, pdA[h]));
        psB[h] = fmaf(d[nt][2], w0s, fmaf(d[nt][3], w1s, psB[h]));
        pdB[h] = fmaf(d[nt][2], w0d, fmaf(d[nt][3], w1d, pdB[h]));
        if (rA < N) *(float2*)&g_h1[(size_t)rA * 128 + n0] = make_float2(d[nt][0], d[nt][1]);
        if (rB < N) *(float2*)&g_h1[(size_t)rB * 128 + n0] = make_float2(d[nt][2], d[nt][3]);
    }
#pragma unroll
    for (int h = 0; h < 4; h++) {
        psA[h] += __shfl_xor_sync(0xffffffffu, psA[h], 1);
        pdA[h] += __shfl_xor_sync(0xffffffffu, pdA[h], 1);
        psB[h] += __shfl_xor_sync(0xffffffffu, psB[h], 1);
        pdB[h] += __shfl_xor_sync(0xffffffffu, pdB[h], 1);
        psA[h] += __shfl_xor_sync(0xffffffffu, psA[h], 2);
        pdA[h] += __shfl_xor_sync(0xffffffffu, pdA[h], 2);
        psB[h] += __shfl_xor_sync(0xffffffffu, psB[h], 2);
        pdB[h] += __shfl_xor_sync(0xffffffffu, pdB[h], 2);
    }
    if (t4 == 0) {
        if (rA < N) {
#pragma unroll
            for (int h = 0; h < 4; h++) { g_as1[rA*4 + h] = psA[h]; g_ad1[rA*4 + h] = pdA[h]; }
        }
        if (rB < N) {
#pragma unroll
            for (int h = 0; h < 4; h++) { g_as1[rB*4 + h] = psB[h]; g_ad1[rB*4 + h] = pdB[h]; }
        }
    }
}

// ============================================================================
// GEMM2 via mma.sync bf16 (3-chain hi/lo) + fused alpha2.
// 128 rows/CTA, N=32, split-K 2 phases. smem ~46KB.
// ============================================================================
#define SMW2_ELE (32 * 72)
#define SM2_TOT  (2 * SMH_ELE * 2 + 2 * SMW2_ELE * 2 + 512)

__global__ __launch_bounds__(256) void k_gemm2_hmma(
    const float* __restrict__ avs, const float* __restrict__ avd, int N)
{
    extern __shared__ char sm[];
    __nv_bfloat16* Ahi = (__nv_bfloat16*)sm;
    __nv_bfloat16* Alo = Ahi + SMH_ELE;
    __nv_bfloat16* Whi = Alo + SMH_ELE;
    __nv_bfloat16* Wlo = Whi + SMW2_ELE;
    float* s_as = (float*)(Wlo + SMW2_ELE);
    float* s_ad = s_as + 32;

    int t = threadIdx.x;
    int r0 = blockIdx.x * 128;
    int wid = t >> 5, lane = t & 31;
    int j = lane >> 3, rin = lane & 7;

    if (t < 32) { s_as[t] = avs[t]; s_ad[t] = avd[t]; }

    int arow = t >> 1, ac0 = (t & 1) * 32;
    int gr_s = r0 + arow;
    bool aval = gr_s < N;
    int wn = t >> 3, wk0 = (t & 7) * 8;   // W: 32 rows x 64 cols per half

    unsigned aOff = ((unsigned)((wid * 16 + (j & 1) * 8 + rin) * 72 + (j >> 1) * 8)) * 2;
    unsigned bOff = ((unsigned)(((j >> 1) * 8 + rin) * 72 + (j & 1) * 8)) * 2;
    unsigned aHiB = s2u(Ahi) + aOff, aLoB = s2u(Alo) + aOff;
    unsigned wHiB = s2u(Whi) + bOff, wLoB = s2u(Wlo) + bOff;

    float d[4][4];
#pragma unroll
    for (int i = 0; i < 4; i++)
#pragma unroll
        for (int q = 0; q < 4; q++) d[i][q] = 0.f;

#pragma unroll 1
    for (int half = 0; half < 2; half++) {
        if (half) __syncthreads();
        {
            const float* xr = g_h1p + (size_t)gr_s * 128 + half * 64 + ac0;
#pragma unroll
            for (int c = 0; c < 32; c += 4) {
                float4 v = aval ? *(const float4*)(xr + c) : make_float4(0, 0, 0, 0);
                float f[4] = {v.x, v.y, v.z, v.w};
                __nv_bfloat16 h[4], l[4];
#pragma unroll
                for (int q = 0; q < 4; q++) {
                    h[q] = __float2bfloat16(f[q]);
                    l[q] = __float2bfloat16(f[q] - __bfloat162float(h[q]));
                }
                int eo = arow * 72 + ac0 + c;
                *(__nv_bfloat162*)&Ahi[eo]     = __nv_bfloat162(h[0], h[1]);
                *(__nv_bfloat162*)&Ahi[eo + 2] = __nv_bfloat162(h[2], h[3]);
                *(__nv_bfloat162*)&Alo[eo]     = __nv_bfloat162(l[0], l[1]);
                *(__nv_bfloat162*)&Alo[eo + 2] = __nv_bfloat162(l[2], l[3]);
            }
        }
        if (t < 256) {                 // stage W2 half: 32 rows x 64 cols
            int so = wn * 136 + half * 64 + wk0;
            int doff = wn * 72 + wk0;
            *(float4*)&Whi[doff] = *(const float4*)&g_w2hi[so];
            *(float4*)&Wlo[doff] = *(const float4*)&g_w2lo[so];
        }
        __syncthreads();

#pragma unroll
        for (int ks = 0; ks < 4; ks++) {
            unsigned ah[4], al[4];
            LDSM4(ah, aHiB + ks * 32);
            LDSM4(al, aLoB + ks * 32);
#pragma unroll
            for (int p = 0; p < 2; p++) {
                unsigned bh[4], bl[4];
                LDSM4(bh, wHiB + p * 2304 + ks * 32);
                LDSM4(bl, wLoB + p * 2304 + ks * 32);
                MMA_BF16(d[2*p],     ah, bh[0], bh[1]);
                MMA_BF16(d[2*p + 1], ah, bh[2], bh[3]);
                MMA_BF16(d[2*p],     al, bh[0], bh[1]);
                MMA_BF16(d[2*p + 1], al, bh[2], bh[3]);
                MMA_BF16(d[2*p],     ah, bl[0], bl[1]);
                MMA_BF16(d[2*p + 1], ah, bl[2], bl[3]);
            }
        }
    }

    int g = lane >> 2, t4 = lane & 3;
    int rA = r0 + wid * 16 + g, rB = rA + 8;
    float psA = 0.f, pdA = 0.f, psB = 0.f, pdB = 0.f;
#pragma unroll
    for (int nt = 0; nt < 4; nt++) {
        int n0 = nt * 8 + 2 * t4;
        float w0s = s_as[n0], w1s = s_as[n0 + 1];
        float w0d = s_ad[n0], w1d = s_ad[n0 + 1];
        psA = fmaf(d[nt][0], w0s, fmaf(d[nt][1], w1s, psA));
        pdA = fmaf(d[nt][0], w0d, fmaf(d[nt][1], w1d, pdA));
        psB = fmaf(d[nt][2], w0s, fmaf(d[nt][3], w1s, psB));
        pdB = fmaf(d[nt][2], w0d, fmaf(d[nt][3], w1d, pdB));
        if (rA < N) *(float2*)&g_h2[(size_t)rA * 32 + n0] = make_float2(d[nt][0], d[nt][1]);
        if (rB < N) *(float2*)&g_h2[(size_t)rB * 32 + n0] = make_float2(d[nt][2], d[nt][3]);
    }
    psA += __shfl_xor_sync(0xffffffffu, psA, 1);
    pdA += __shfl_xor_sync(0xffffffffu, pdA, 1);
    psB += __shfl_xor_sync(0xffffffffu, psB, 1);
    pdB += __shfl_xor_sync(0xffffffffu, pdB, 1);
    psA += __shfl_xor_sync(0xffffffffu, psA, 2);
    pdA += __shfl_xor_sync(0xffffffffu, pdA, 2);
    psB += __shfl_xor_sync(0xffffffffu, psB, 2);
    pdB += __shfl_xor_sync(0xffffffffu, pdB, 2);
    if (t4 == 0) {
        if (rA < N) { g_as2[rA] = psA; g_ad2[rA] = pdA; }
        if (rB < N) { g_as2[rB] = psB; g_ad2[rB] = pdB; }
    }
}

// ---------------- GAT1 gather: warp per dst node -----------------------------
__global__ __launch_bounds__(256) void k_gat1(
    const float* __restrict__ b1,
    const float* __restrict__ bg, const float* __restrict__ bb,
    const float* __restrict__ bm, const float* __restrict__ bv, int N)
{
    int gw   = (blockIdx.x * blockDim.x + threadIdx.x) >> 5;
    int lane = threadIdx.x & 31;
    if (gw >= N) return;
    int d    = gw;
    int head = lane >> 3;

    float adv = __ldg(&g_ad1[d * 4 + head]);

    float wself = __expf(lrelu(__ldg(&g_as1[d * 4 + head]) + adv));
    float4 hv = *(const float4*)&g_h1[(size_t)d * 128 + lane * 4];
    float4 acc = make_float4(wself*hv.x, wself*hv.y, wself*hv.z, wself*hv.w);
    float wsum = wself;

    int deg = min(g_deg[d], CAP);
    const int* lst = &g_csr[d * CAP];
    for (int j0 = 0; j0 < deg; j0 += 32) {
        int sid = (j0 + lane < deg) ? lst[j0 + lane] : 0;
        int m = min(32, deg - j0);
#pragma unroll 4
        for (int jj = 0; jj < m; jj++) {
            int s = __shfl_sync(0xffffffffu, sid, jj);
            float we = __expf(lrelu(__ldg(&g_as1[s * 4 + head]) + adv));
            float4 h = *(const float4*)&g_h1[(size_t)s * 128 + lane * 4];
            acc.x = fmaf(we, h.x, acc.x);
            acc.y = fmaf(we, h.y, acc.y);
            acc.z = fmaf(we, h.z, acc.z);
            acc.w = fmaf(we, h.w, acc.w);
            wsum += we;
        }
    }

    float inv = 1.f / wsum;
    float4 bc = *(const float4*)&b1[lane * 4];
    float4 g4 = *(const float4*)&bg[lane * 4];
    float4 b4 = *(const float4*)&bb[lane * 4];
    float4 m4 = *(const float4*)&bm[lane * 4];
    float4 v4 = *(const float4*)&bv[lane * 4];
    float4 o;
    o.x = (acc.x * inv + bc.x - m4.x) * rsqrtf(v4.x + BN_EPS) * g4.x + b4.x;
    o.y = (acc.y * inv + bc.y - m4.y) * rsqrtf(v4.y + BN_EPS) * g4.y + b4.y;
    o.z = (acc.z * inv + bc.z - m4.z) * rsqrtf(v4.z + BN_EPS) * g4.z + b4.z;
    o.w = (acc.w * inv + bc.w - m4.w) * rsqrtf(v4.w + BN_EPS) * g4.w + b4.w;
    o.x = o.x > 0.f ? o.x : expm1f(o.x);
    o.y = o.y > 0.f ? o.y : expm1f(o.y);
    o.z = o.z > 0.f ? o.z : expm1f(o.z);
    o.w = o.w > 0.f ? o.w : expm1f(o.w);
    *(float4*)&g_h1p[(size_t)d * 128 + lane * 4] = o;
}

// ---------------- GAT2 gather: warp per dst node (C=32, 1 head) --------------
__global__ __launch_bounds__(256) void k_gat2(const float* __restrict__ b2, int N) {
    int gw   = (blockIdx.x * blockDim.x + threadIdx.x) >> 5;
    int lane = threadIdx.x & 31;
    if (gw >= N) return;
    int d = gw;

    float adv = __ldg(&g_ad2[d]);
    float w = __expf(lrelu(__ldg(&g_as2[d]) + adv));
    float acc = w * g_h2[(size_t)d * 32 + lane];
    float wsum = w;

    int deg = min(g_deg[d], CAP);
    const int* lst = &g_csr[d * CAP];
    for (int j0 = 0; j0 < deg; j0 += 32) {
        int m = min(32, deg - j0);
        int sid = (lane < m) ? lst[j0 + lane] : 0;
        float wl = (lane < m) ? __expf(lrelu(__ldg(&g_as2[sid]) + adv)) : 0.f;
#pragma unroll 4
        for (int jj = 0; jj < m; jj++) {
            int s  = __shfl_sync(0xffffffffu, sid, jj);
            float we = __shfl_sync(0xffffffffu, wl, jj);
            acc = fmaf(we, __ldg(&g_h2[(size_t)s * 32 + lane]), acc);
            wsum += we;
        }
    }
    g_o2[(size_t)d * 32 + lane] = acc / wsum + __ldg(&b2[lane]);
    if (lane == 0) g_deg[d] = 0;
}

// ---------------- final: per-node MLP tail + log_softmax ---------------------
__global__ void k_final(const float* __restrict__ ctx,
                        const float* __restrict__ rw1, const float* __restrict__ rb1,
                        const float* __restrict__ rw2, const float* __restrict__ rb2,
                        const float* __restrict__ dw,  const float* __restrict__ db,
                        const float* __restrict__ cw,  const float* __restrict__ cb,
                        float* __restrict__ out, int N) {
    __shared__ float sw[2666];
    int t = threadIdx.x;
    for (int i = t; i < 192;  i += 256) sw[i]        = rw1[i];
    for (int i = t; i < 32;   i += 256) sw[192 + i]  = rb1[i];
    for (int i = t; i < 1024; i += 256) sw[224 + i]  = rw2[i];
    for (int i = t; i < 32;   i += 256) sw[1248 + i] = rb2[i];
    for (int i = t; i < 1024; i += 256) sw[1280 + i] = dw[i];
    for (int i = t; i < 32;   i += 256) sw[2304 + i] = db[i];
    for (int i = t; i < 320;  i += 256) sw[2336 + i] = cw[i];
    for (int i = t; i < 10;   i += 256) sw[2656 + i] = cb[i];
    __syncthreads();

    int n = blockIdx.x * 256 + t;
    if (n >= N) return;

    float c0 = ctx[n * 6 + 0], c1 = ctx[n * 6 + 1], c2 = ctx[n * 6 + 2];
    float c3 = ctx[n * 6 + 3], c4 = ctx[n * 6 + 4], c5 = ctx[n * 6 + 5];

    float t1[32];
#pragma unroll
    for (int j = 0; j < 32; j++) {
        float v = sw[192 + j];
        v = fmaf(c0, sw[0 * 32 + j], v);
        v = fmaf(c1, sw[1 * 32 + j], v);
        v = fmaf(c2, sw[2 * 32 + j], v);
        v = fmaf(c3, sw[3 * 32 + j], v);
        v = fmaf(c4, sw[4 * 32 + j], v);
        v = fmaf(c5, sw[5 * 32 + j], v);
        t1[j] = fmaxf(v, 0.f);
    }
    float ex[32];
#pragma unroll
    for (int j = 0; j < 32; j++) {
        float v = sw[1248 + j];
#pragma unroll
        for (int k = 0; k < 32; k++) v = fmaf(t1[k], sw[224 + k * 32 + j], v);
        ex[j] = v;
    }
    float comb[32];
#pragma unroll
    for (int j = 0; j < 32; j++) {
        float rec = sw[2304 + j];
#pragma unroll
        for (int k = 0; k < 32; k++) rec = fmaf(ex[k], sw[1280 + k * 32 + j], rec);
        comb[j] = g_o2[(size_t)n * 32 + j] + RECON_W * rec;
    }
    float lg[10];
#pragma unroll
    for (int c = 0; c < 10; c++) {
        float v = sw[2656 + c];
#pragma unroll
        for (int j = 0; j < 32; j++) v = fmaf(comb[j], sw[2336 + j * 10 + c], v);
        lg[c] = v;
    }
    float m = lg[0];
#pragma unroll
    for (int c = 1; c < 10; c++) m = fmaxf(m, lg[c]);
    float sum = 0.f;
#pragma unroll
    for (int c = 0; c < 10; c++) sum += expf(lg[c] - m);
    float lse = m + logf(sum);
#pragma unroll
    for (int c = 0; c < 10; c++) out[n * 10 + c] = lg[c] - lse;
#pragma unroll
    for (int j = 0; j < 32; j++) out[N * 10 + n * 32 + j] = ex[j];
}

// ---------------- launch ------------------------------------------------------
extern "C" void kernel_launch(void* const* d_in, const int* in_sizes, int n_in,
                              void* d_out, int out_size) {
    const float* x    = (const float*)d_in[0];
    const int*   ei   = (const int*)  d_in[1];
    const float* ctx  = (const float*)d_in[2];
    const float* W1   = (const float*)d_in[3];
    const float* as1  = (const float*)d_in[4];
    const float* ad1  = (const float*)d_in[5];
    const float* b1   = (const float*)d_in[6];
    const float* bng  = (const float*)d_in[7];
    const float* bnb  = (const float*)d_in[8];
    const float* bnm  = (const float*)d_in[9];
    const float* bnv  = (const float*)d_in[10];
    const float* W2   = (const float*)d_in[11];
    const float* as2  = (const float*)d_in[12];
    const float* ad2  = (const float*)d_in[13];
    const float* b2   = (const float*)d_in[14];
    const float* rw1  = (const float*)d_in[15];
    const float* rb1  = (const float*)d_in[16];
    const float* rw2  = (const float*)d_in[17];
    const float* rb2  = (const float*)d_in[18];
    const float* dw   = (const float*)d_in[19];
    const float* db   = (const float*)d_in[20];
    const float* cw   = (const float*)d_in[21];
    const float* cb   = (const float*)d_in[22];
    float* out = (float*)d_out;

    int N = in_sizes[0] / 128;
    int E = in_sizes[1] / 2;

    static bool attr_set = false;
    if (!attr_set) {
        cudaFuncSetAttribute(k_gemm1_hmma, cudaFuncAttributeMaxDynamicSharedMemorySize, SM_TOT);
        cudaFuncSetAttribute(k_gemm2_hmma, cudaFuncAttributeMaxDynamicSharedMemorySize, SM2_TOT);
        attr_set = true;
    }

    // fused adjacency build + W1/W2 prep
    k_fill_prep<<<80 + (E + 255) / 256, 256>>>(ei, W1, W2, E);

    // layer 1
    k_gemm1_hmma<<<(N + 127) / 128, 256, SM_TOT>>>(x, as1, ad1, N);
    k_gat1<<<(N * 32 + 255) / 256, 256>>>(b1, bng, bnb, bnm, bnv, N);

    // layer 2
    k_gemm2_hmma<<<(N + 127) / 128, 256, SM2_TOT>>>(as2, ad2, N);
    k_gat2<<<(N * 32 + 255) / 256, 256>>>(b2, N);

    k_final<<<(N + 255) / 256, 256>>>(ctx, rw1, rb1, rw2, rb2, dw, db, cw, cb,
                                      out, N);
}

// round 9
// speedup vs baseline: 1.3002x; 1.0484x over previous
#include <cuda_runtime.h>
#include <cuda_bf16.h>
#include <math.h>

#define MAXN 100000
#define CAP  128
#define NEG_SLOPE 0.2f
#define BN_EPS 1e-5f
#define RECON_W 0.1f

// ---------------- scratch (device globals) ----------------------------------
__device__ float g_h1 [MAXN * 128];   // x @ W1
__device__ float g_h1p[MAXN * 128];   // after GAT1 + BN + ELU
__device__ float g_h2 [MAXN * 32];    // h1p @ W2
__device__ float g_o2 [MAXN * 32];    // after GAT2 + bias
__device__ float g_as1[MAXN * 4];
__device__ float g_ad1[MAXN * 4];
__device__ float g_as2[MAXN];
__device__ float g_ad2[MAXN];
__device__ int   g_deg[MAXN];         // zeroed invariant: reset by k_gat2
__device__ int   g_csr[MAXN * CAP];   // per-dst src lists (bucketed)
__device__ __nv_bfloat16 g_w1hi[128 * 136];  // W1^T bf16 hi, n-major padded
__device__ __nv_bfloat16 g_w1lo[128 * 136];
__device__ __nv_bfloat16 g_w2hi[32 * 136];   // W2^T bf16 hi, n-major padded
__device__ __nv_bfloat16 g_w2lo[32 * 136];

__device__ __forceinline__ float lrelu(float t) { return t > 0.f ? t : NEG_SLOPE * t; }

__device__ __forceinline__ unsigned s2u(const void* p) {
    unsigned a;
    asm("{ .reg .u64 t; cvta.to.shared.u64 t, %1; cvt.u32.u64 %0, t; }" : "=r"(a) : "l"(p));
    return a;
}

#define LDSM4(f, addr) \
    asm volatile("ldmatrix.sync.aligned.m8n8.x4.shared.b16 {%0,%1,%2,%3}, [%4];" \
        : "=r"((f)[0]),"=r"((f)[1]),"=r"((f)[2]),"=r"((f)[3]) : "r"(addr))

#define MMA_BF16(dd, a, b0, b1) \
    asm volatile("mma.sync.aligned.m16n8k16.row.col.f32.bf16.bf16.f32 " \
        "{%0,%1,%2,%3}, {%4,%5,%6,%7}, {%8,%9}, {%0,%1,%2,%3};" \
        : "+f"((dd)[0]),"+f"((dd)[1]),"+f"((dd)[2]),"+f"((dd)[3]) \
        : "r"((a)[0]),"r"((a)[1]),"r"((a)[2]),"r"((a)[3]), "r"(b0),"r"(b1))

// ---------------- fused adjacency build + W1/W2 prep -------------------------
__global__ void k_fill_prep(const int* __restrict__ ei, const float* __restrict__ W1,
                            const float* __restrict__ W2, int E) {
    int b = blockIdx.x;
    if (b < 64) {                       // W1: [128,128] k-major -> [n][136]
        int i = b * 256 + threadIdx.x;
        int k = i >> 7, n = i & 127;
        float v = W1[i];
        __nv_bfloat16 hi = __float2bfloat16(v);
        __nv_bfloat16 lo = __float2bfloat16(v - __bfloat162float(hi));
        g_w1hi[n * 136 + k] = hi;
        g_w1lo[n * 136 + k] = lo;
        return;
    }
    if (b < 80) {                       // W2: [128,32] k-major -> [n][136]
        int i = (b - 64) * 256 + threadIdx.x;
        int k = i >> 5, n = i & 31;
        float v = W2[i];
        __nv_bfloat16 hi = __float2bfloat16(v);
        __nv_bfloat16 lo = __float2bfloat16(v - __bfloat162float(hi));
        g_w2hi[n * 136 + k] = hi;
        g_w2lo[n * 136 + k] = lo;
        return;
    }
    int e = (b - 80) * 256 + threadIdx.x;
    if (e >= E) return;
    int s = ei[e], d = ei[E + e];
    int pos = atomicAdd(&g_deg[d], 1);
    if (pos < CAP) g_csr[d * CAP + pos] = s;
}

// ============================================================================
// GEMM1 via mma.sync bf16 (3-chain hi/lo) + fused alpha1. Split-K, 2 phases.
// ============================================================================
#define SMH_ELE (128 * 72)
#define SM_TOT  (4 * SMH_ELE * 2 + 1024)

__global__ __launch_bounds__(256) void k_gemm1_hmma(
    const float* __restrict__ x,
    const float* __restrict__ avs, const float* __restrict__ avd, int N)
{
    extern __shared__ char sm[];
    __nv_bfloat16* Ahi = (__nv_bfloat16*)sm;
    __nv_bfloat16* Alo = Ahi + SMH_ELE;
    __nv_bfloat16* Whi = Alo + SMH_ELE;
    __nv_bfloat16* Wlo = Whi + SMH_ELE;
    float* s_as = (float*)(Wlo + SMH_ELE);
    float* s_ad = s_as + 128;

    int t = threadIdx.x;
    int r0 = blockIdx.x * 128;
    int wid = t >> 5, lane = t & 31;
    int j = lane >> 3, rin = lane & 7;

    if (t < 128) { s_as[t] = avs[t]; s_ad[t] = avd[t]; }

    int arow = t >> 1, ac0 = (t & 1) * 32;
    int gr_s = r0 + arow;
    bool aval = gr_s < N;
    int wn = t >> 1, wk0 = (t & 1) * 32;

    unsigned aOff = ((unsigned)((wid * 16 + (j & 1) * 8 + rin) * 72 + (j >> 1) * 8)) * 2;
    unsigned bOff = ((unsigned)(((j >> 1) * 8 + rin) * 72 + (j & 1) * 8)) * 2;
    unsigned aHiB = s2u(Ahi) + aOff, aLoB = s2u(Alo) + aOff;
    unsigned wHiB = s2u(Whi) + bOff, wLoB = s2u(Wlo) + bOff;

    float d[16][4];
#pragma unroll
    for (int i = 0; i < 16; i++)
#pragma unroll
        for (int q = 0; q < 4; q++) d[i][q] = 0.f;

#pragma unroll 1
    for (int half = 0; half < 2; half++) {
        if (half) __syncthreads();
        {
            const float* xr = x + (size_t)gr_s * 128 + half * 64 + ac0;
#pragma unroll
            for (int c = 0; c < 32; c += 4) {
                float4 v = aval ? *(const float4*)(xr + c) : make_float4(0, 0, 0, 0);
                float f[4] = {v.x, v.y, v.z, v.w};
                __nv_bfloat16 h[4], l[4];
#pragma unroll
                for (int q = 0; q < 4; q++) {
                    h[q] = __float2bfloat16(f[q]);
                    l[q] = __float2bfloat16(f[q] - __bfloat162float(h[q]));
                }
                int eo = arow * 72 + ac0 + c;
                *(__nv_bfloat162*)&Ahi[eo]     = __nv_bfloat162(h[0], h[1]);
                *(__nv_bfloat162*)&Ahi[eo + 2] = __nv_bfloat162(h[2], h[3]);
                *(__nv_bfloat162*)&Alo[eo]     = __nv_bfloat162(l[0], l[1]);
                *(__nv_bfloat162*)&Alo[eo + 2] = __nv_bfloat162(l[2], l[3]);
            }
        }
        {
#pragma unroll
            for (int q = 0; q < 4; q++) {
                int so = wn * 136 + half * 64 + wk0 + q * 8;
                int doff = wn * 72 + wk0 + q * 8;
                *(float4*)&Whi[doff] = *(const float4*)&g_w1hi[so];
                *(float4*)&Wlo[doff] = *(const float4*)&g_w1lo[so];
            }
        }
        __syncthreads();

#pragma unroll
        for (int ks = 0; ks < 4; ks++) {
            unsigned ah[4], al[4];
            LDSM4(ah, aHiB + ks * 32);
            LDSM4(al, aLoB + ks * 32);
#pragma unroll
            for (int p = 0; p < 8; p++) {
                unsigned bh[4], bl[4];
                LDSM4(bh, wHiB + p * 2304 + ks * 32);
                LDSM4(bl, wLoB + p * 2304 + ks * 32);
                MMA_BF16(d[2*p],     ah, bh[0], bh[1]);
                MMA_BF16(d[2*p + 1], ah, bh[2], bh[3]);
                MMA_BF16(d[2*p],     al, bh[0], bh[1]);
                MMA_BF16(d[2*p + 1], al, bh[2], bh[3]);
                MMA_BF16(d[2*p],     ah, bl[0], bl[1]);
                MMA_BF16(d[2*p + 1], ah, bl[2], bl[3]);
            }
        }
    }

    int g = lane >> 2, t4 = lane & 3;
    int rA = r0 + wid * 16 + g, rB = rA + 8;
    float psA[4] = {0,0,0,0}, pdA[4] = {0,0,0,0};
    float psB[4] = {0,0,0,0}, pdB[4] = {0,0,0,0};
#pragma unroll
    for (int nt = 0; nt < 16; nt++) {
        int n0 = nt * 8 + 2 * t4;
        float w0s = s_as[n0], w1s = s_as[n0 + 1];
        float w0d = s_ad[n0], w1d = s_ad[n0 + 1];
        int h = nt >> 2;
        psA[h] = fmaf(d[nt][0], w0s, fmaf(d[nt][1], w1s, psA[h]));
        pdA[h] = fmaf(d[nt][0], w0d, fmaf(d[nt][1], w1d, pdA[h]));
        psB[h] = fmaf(d[nt][2], w0s, fmaf(d[nt][3], w1s, psB[h]));
        pdB[h] = fmaf(d[nt][2], w0d, fmaf(d[nt][3], w1d, pdB[h]));
        if (rA < N) *(float2*)&g_h1[(size_t)rA * 128 + n0] = make_float2(d[nt][0], d[nt][1]);
        if (rB < N) *(float2*)&g_h1[(size_t)rB * 128 + n0] = make_float2(d[nt][2], d[nt][3]);
    }
#pragma unroll
    for (int h = 0; h < 4; h++) {
        psA[h] += __shfl_xor_sync(0xffffffffu, psA[h], 1);
        pdA[h] += __shfl_xor_sync(0xffffffffu, pdA[h], 1);
        psB[h] += __shfl_xor_sync(0xffffffffu, psB[h], 1);
        pdB[h] += __shfl_xor_sync(0xffffffffu, pdB[h], 1);
        psA[h] += __shfl_xor_sync(0xffffffffu, psA[h], 2);
        pdA[h] += __shfl_xor_sync(0xffffffffu, pdA[h], 2);
        psB[h] += __shfl_xor_sync(0xffffffffu, psB[h], 2);
        pdB[h] += __shfl_xor_sync(0xffffffffu, pdB[h], 2);
    }
    if (t4 == 0) {
        if (rA < N) {
#pragma unroll
            for (int h = 0; h < 4; h++) { g_as1[rA*4 + h] = psA[h]; g_ad1[rA*4 + h] = pdA[h]; }
        }
        if (rB < N) {
#pragma unroll
            for (int h = 0; h < 4; h++) { g_as1[rB*4 + h] = psB[h]; g_ad1[rB*4 + h] = pdB[h]; }
        }
    }
}

// ============================================================================
// GEMM2 via mma.sync bf16 (3-chain hi/lo) + fused alpha2.
// 64 rows/CTA, N=32, split-K 2 phases, smem ~29KB -> high occupancy.
// 8 warps = 4 m-tiles (16 rows) x 2 n-halves (16 cols).
// ============================================================================
#define SM2A_ELE (64 * 72)
#define SM2W_ELE (32 * 72)
#define SM2_TOT  (2 * SM2A_ELE * 2 + 2 * SM2W_ELE * 2 + 2 * 32 * 4 + 2 * 128 * 4)

__global__ __launch_bounds__(256) void k_gemm2_hmma(
    const float* __restrict__ avs, const float* __restrict__ avd, int N)
{
    extern __shared__ char sm[];
    __nv_bfloat16* Ahi = (__nv_bfloat16*)sm;
    __nv_bfloat16* Alo = Ahi + SM2A_ELE;
    __nv_bfloat16* Whi = Alo + SM2A_ELE;
    __nv_bfloat16* Wlo = Whi + SM2W_ELE;
    float* s_as = (float*)(Wlo + SM2W_ELE);
    float* s_ad = s_as + 32;
    float* ps_part = s_ad + 32;        // [64][2]
    float* pd_part = ps_part + 128;    // [64][2]

    int t = threadIdx.x;
    int r0 = blockIdx.x * 64;
    int wid = t >> 5, lane = t & 31;
    int j = lane >> 3, rin = lane & 7;

    if (t < 32) { s_as[t] = avs[t]; s_ad[t] = avd[t]; }

    int arow = t >> 2, ac0 = (t & 3) * 16;
    int gr_s = r0 + arow;
    bool aval = gr_s < N;
    int wn = t >> 3, wk0 = (t & 7) * 8;

    unsigned aOff = ((unsigned)(((wid >> 1) * 16 + (j & 1) * 8 + rin) * 72 + (j >> 1) * 8)) * 2;
    unsigned bOff = ((unsigned)(((wid & 1) * 16 + (j >> 1) * 8 + rin) * 72 + (j & 1) * 8)) * 2;
    unsigned aHiB = s2u(Ahi) + aOff, aLoB = s2u(Alo) + aOff;
    unsigned wHiB = s2u(Whi) + bOff, wLoB = s2u(Wlo) + bOff;

    float d[2][4];
#pragma unroll
    for (int i = 0; i < 2; i++)
#pragma unroll
        for (int q = 0; q < 4; q++) d[i][q] = 0.f;

#pragma unroll 1
    for (int half = 0; half < 2; half++) {
        if (half) __syncthreads();
        {
            const float* xr = g_h1p + (size_t)gr_s * 128 + half * 64 + ac0;
#pragma unroll
            for (int c = 0; c < 16; c += 4) {
                float4 v = aval ? *(const float4*)(xr + c) : make_float4(0, 0, 0, 0);
                float f[4] = {v.x, v.y, v.z, v.w};
                __nv_bfloat16 h[4], l[4];
#pragma unroll
                for (int q = 0; q < 4; q++) {
                    h[q] = __float2bfloat16(f[q]);
                    l[q] = __float2bfloat16(f[q] - __bfloat162float(h[q]));
                }
                int eo = arow * 72 + ac0 + c;
                *(__nv_bfloat162*)&Ahi[eo]     = __nv_bfloat162(h[0], h[1]);
                *(__nv_bfloat162*)&Ahi[eo + 2] = __nv_bfloat162(h[2], h[3]);
                *(__nv_bfloat162*)&Alo[eo]     = __nv_bfloat162(l[0], l[1]);
                *(__nv_bfloat162*)&Alo[eo + 2] = __nv_bfloat162(l[2], l[3]);
            }
        }
        {   // stage W2 half: 32 n-rows x 64 k-cols
            int so = wn * 136 + half * 64 + wk0;
            int doff = wn * 72 + wk0;
            *(float4*)&Whi[doff] = *(const float4*)&g_w2hi[so];
            *(float4*)&Wlo[doff] = *(const float4*)&g_w2lo[so];
        }
        __syncthreads();

#pragma unroll
        for (int ks = 0; ks < 4; ks++) {
            unsigned ah[4], al[4], bh[4], bl[4];
            LDSM4(ah, aHiB + ks * 32);
            LDSM4(al, aLoB + ks * 32);
            LDSM4(bh, wHiB + ks * 32);
            LDSM4(bl, wLoB + ks * 32);
            MMA_BF16(d[0], ah, bh[0], bh[1]);
            MMA_BF16(d[1], ah, bh[2], bh[3]);
            MMA_BF16(d[0], al, bh[0], bh[1]);
            MMA_BF16(d[1], al, bh[2], bh[3]);
            MMA_BF16(d[0], ah, bl[0], bl[1]);
            MMA_BF16(d[1], ah, bl[2], bl[3]);
        }
    }

    int g = lane >> 2, t4 = lane & 3;
    int lA = (wid >> 1) * 16 + g, lB = lA + 8;
    int rA = r0 + lA, rB = r0 + lB;
    int nbase = (wid & 1) * 16;
    float psA = 0.f, pdA = 0.f, psB = 0.f, pdB = 0.f;
#pragma unroll
    for (int nt = 0; nt < 2; nt++) {
        int n0 = nbase + nt * 8 + 2 * t4;
        float w0s = s_as[n0], w1s = s_as[n0 + 1];
        float w0d = s_ad[n0], w1d = s_ad[n0 + 1];
        psA = fmaf(d[nt][0], w0s, fmaf(d[nt][1], w1s, psA));
        pdA = fmaf(d[nt][0], w0d, fmaf(d[nt][1], w1d, pdA));
        psB = fmaf(d[nt][2], w0s, fmaf(d[nt][3], w1s, psB));
        pdB = fmaf(d[nt][2], w0d, fmaf(d[nt][3], w1d, pdB));
        if (rA < N) *(float2*)&g_h2[(size_t)rA * 32 + n0] = make_float2(d[nt][0], d[nt][1]);
        if (rB < N) *(float2*)&g_h2[(size_t)rB * 32 + n0] = make_float2(d[nt][2], d[nt][3]);
    }
    psA += __shfl_xor_sync(0xffffffffu, psA, 1);
    pdA += __shfl_xor_sync(0xffffffffu, pdA, 1);
    psB += __shfl_xor_sync(0xffffffffu, psB, 1);
    pdB += __shfl_xor_sync(0xffffffffu, pdB, 1);
    psA += __shfl_xor_sync(0xffffffffu, psA, 2);
    pdA += __shfl_xor_sync(0xffffffffu, pdA, 2);
    psB += __shfl_xor_sync(0xffffffffu, psB, 2);
    pdB += __shfl_xor_sync(0xffffffffu, pdB, 2);
    if (t4 == 0) {
        int nh = wid & 1;
        ps_part[lA * 2 + nh] = psA;  pd_part[lA * 2 + nh] = pdA;
        ps_part[lB * 2 + nh] = psB;  pd_part[lB * 2 + nh] = pdB;
    }
    __syncthreads();
    if (t < 64) {
        int gr = r0 + t;
        if (gr < N) {
            g_as2[gr] = ps_part[t * 2] + ps_part[t * 2 + 1];
            g_ad2[gr] = pd_part[t * 2] + pd_part[t * 2 + 1];
        }
    }
}

// ---------------- GAT1 gather: warp per dst node -----------------------------
__global__ __launch_bounds__(256) void k_gat1(
    const float* __restrict__ b1,
    const float* __restrict__ bg, const float* __restrict__ bb,
    const float* __restrict__ bm, const float* __restrict__ bv, int N)
{
    int gw   = (blockIdx.x * blockDim.x + threadIdx.x) >> 5;
    int lane = threadIdx.x & 31;
    if (gw >= N) return;
    int d    = gw;
    int head = lane >> 3;

    float adv = __ldg(&g_ad1[d * 4 + head]);

    float wself = __expf(lrelu(__ldg(&g_as1[d * 4 + head]) + adv));
    float4 hv = *(const float4*)&g_h1[(size_t)d * 128 + lane * 4];
    float4 acc = make_float4(wself*hv.x, wself*hv.y, wself*hv.z, wself*hv.w);
    float wsum = wself;

    int deg = min(g_deg[d], CAP);
    const int* lst = &g_csr[d * CAP];
    for (int j0 = 0; j0 < deg; j0 += 32) {
        int sid = (j0 + lane < deg) ? lst[j0 + lane] : 0;
        int m = min(32, deg - j0);
#pragma unroll 4
        for (int jj = 0; jj < m; jj++) {
            int s = __shfl_sync(0xffffffffu, sid, jj);
            float we = __expf(lrelu(__ldg(&g_as1[s * 4 + head]) + adv));
            float4 h = *(const float4*)&g_h1[(size_t)s * 128 + lane * 4];
            acc.x = fmaf(we, h.x, acc.x);
            acc.y = fmaf(we, h.y, acc.y);
            acc.z = fmaf(we, h.z, acc.z);
            acc.w = fmaf(we, h.w, acc.w);
            wsum += we;
        }
    }

    float inv = 1.f / wsum;
    float4 bc = *(const float4*)&b1[lane * 4];
    float4 g4 = *(const float4*)&bg[lane * 4];
    float4 b4 = *(const float4*)&bb[lane * 4];
    float4 m4 = *(const float4*)&bm[lane * 4];
    float4 v4 = *(const float4*)&bv[lane * 4];
    float4 o;
    o.x = (acc.x * inv + bc.x - m4.x) * rsqrtf(v4.x + BN_EPS) * g4.x + b4.x;
    o.y = (acc.y * inv + bc.y - m4.y) * rsqrtf(v4.y + BN_EPS) * g4.y + b4.y;
    o.z = (acc.z * inv + bc.z - m4.z) * rsqrtf(v4.z + BN_EPS) * g4.z + b4.z;
    o.w = (acc.w * inv + bc.w - m4.w) * rsqrtf(v4.w + BN_EPS) * g4.w + b4.w;
    o.x = o.x > 0.f ? o.x : expm1f(o.x);
    o.y = o.y > 0.f ? o.y : expm1f(o.y);
    o.z = o.z > 0.f ? o.z : expm1f(o.z);
    o.w = o.w > 0.f ? o.w : expm1f(o.w);
    *(float4*)&g_h1p[(size_t)d * 128 + lane * 4] = o;
}

// ---------------- GAT2 gather: warp per dst node (C=32, 1 head) --------------
__global__ __launch_bounds__(256) void k_gat2(const float* __restrict__ b2, int N) {
    int gw   = (blockIdx.x * blockDim.x + threadIdx.x) >> 5;
    int lane = threadIdx.x & 31;
    if (gw >= N) return;
    int d = gw;

    float adv = __ldg(&g_ad2[d]);
    float w = __expf(lrelu(__ldg(&g_as2[d]) + adv));
    float acc = w * g_h2[(size_t)d * 32 + lane];
    float wsum = w;

    int deg = min(g_deg[d], CAP);
    const int* lst = &g_csr[d * CAP];
    for (int j0 = 0; j0 < deg; j0 += 32) {
        int m = min(32, deg - j0);
        int sid = (lane < m) ? lst[j0 + lane] : 0;
        float wl = (lane < m) ? __expf(lrelu(__ldg(&g_as2[sid]) + adv)) : 0.f;
#pragma unroll 4
        for (int jj = 0; jj < m; jj++) {
            int s  = __shfl_sync(0xffffffffu, sid, jj);
            float we = __shfl_sync(0xffffffffu, wl, jj);
            acc = fmaf(we, __ldg(&g_h2[(size_t)s * 32 + lane]), acc);
            wsum += we;
        }
    }
    g_o2[(size_t)d * 32 + lane] = acc / wsum + __ldg(&b2[lane]);
    if (lane == 0) g_deg[d] = 0;
}

// ---------------- final: per-node MLP tail + log_softmax ---------------------
__global__ void k_final(const float* __restrict__ ctx,
                        const float* __restrict__ rw1, const float* __restrict__ rb1,
                        const float* __restrict__ rw2, const float* __restrict__ rb2,
                        const float* __restrict__ dw,  const float* __restrict__ db,
                        const float* __restrict__ cw,  const float* __restrict__ cb,
                        float* __restrict__ out, int N) {
    __shared__ float sw[2666];
    int t = threadIdx.x;
    for (int i = t; i < 192;  i += 256) sw[i]        = rw1[i];
    for (int i = t; i < 32;   i += 256) sw[192 + i]  = rb1[i];
    for (int i = t; i < 1024; i += 256) sw[224 + i]  = rw2[i];
    for (int i = t; i < 32;   i += 256) sw[1248 + i] = rb2[i];
    for (int i = t; i < 1024; i += 256) sw[1280 + i] = dw[i];
    for (int i = t; i < 32;   i += 256) sw[2304 + i] = db[i];
    for (int i = t; i < 320;  i += 256) sw[2336 + i] = cw[i];
    for (int i = t; i < 10;   i += 256) sw[2656 + i] = cb[i];
    __syncthreads();

    int n = blockIdx.x * 256 + t;
    if (n >= N) return;

    float c0 = ctx[n * 6 + 0], c1 = ctx[n * 6 + 1], c2 = ctx[n * 6 + 2];
    float c3 = ctx[n * 6 + 3], c4 = ctx[n * 6 + 4], c5 = ctx[n * 6 + 5];

    float t1[32];
#pragma unroll
    for (int j = 0; j < 32; j++) {
        float v = sw[192 + j];
        v = fmaf(c0, sw[0 * 32 + j], v);
        v = fmaf(c1, sw[1 * 32 + j], v);
        v = fmaf(c2, sw[2 * 32 + j], v);
        v = fmaf(c3, sw[3 * 32 + j], v);
        v = fmaf(c4, sw[4 * 32 + j], v);
        v = fmaf(c5, sw[5 * 32 + j], v);
        t1[j] = fmaxf(v, 0.f);
    }
    float ex[32];
#pragma unroll
    for (int j = 0; j < 32; j++) {
        float v = sw[1248 + j];
#pragma unroll
        for (int k = 0; k < 32; k++) v = fmaf(t1[k], sw[224 + k * 32 + j], v);
        ex[j] = v;
    }
    float comb[32];
#pragma unroll
    for (int j = 0; j < 32; j++) {
        float rec = sw[2304 + j];
#pragma unroll
        for (int k = 0; k < 32; k++) rec = fmaf(ex[k], sw[1280 + k * 32 + j], rec);
        comb[j] = g_o2[(size_t)n * 32 + j] + RECON_W * rec;
    }
    float lg[10];
#pragma unroll
    for (int c = 0; c < 10; c++) {
        float v = sw[2656 + c];
#pragma unroll
        for (int j = 0; j < 32; j++) v = fmaf(comb[j], sw[2336 + j * 10 + c], v);
        lg[c] = v;
    }
    float m = lg[0];
#pragma unroll
    for (int c = 1; c < 10; c++) m = fmaxf(m, lg[c]);
    float sum = 0.f;
#pragma unroll
    for (int c = 0; c < 10; c++) sum += expf(lg[c] - m);
    float lse = m + logf(sum);
#pragma unroll
    for (int c = 0; c < 10; c++) out[n * 10 + c] = lg[c] - lse;
#pragma unroll
    for (int j = 0; j < 32; j++) out[N * 10 + n * 32 + j] = ex[j];
}

// ---------------- launch ------------------------------------------------------
extern "C" void kernel_launch(void* const* d_in, const int* in_sizes, int n_in,
                              void* d_out, int out_size) {
    const float* x    = (const float*)d_in[0];
    const int*   ei   = (const int*)  d_in[1];
    const float* ctx  = (const float*)d_in[2];
    const float* W1   = (const float*)d_in[3];
    const float* as1  = (const float*)d_in[4];
    const float* ad1  = (const float*)d_in[5];
    const float* b1   = (const float*)d_in[6];
    const float* bng  = (const float*)d_in[7];
    const float* bnb  = (const float*)d_in[8];
    const float* bnm  = (const float*)d_in[9];
    const float* bnv  = (const float*)d_in[10];
    const float* W2   = (const float*)d_in[11];
    const float* as2  = (const float*)d_in[12];
    const float* ad2  = (const float*)d_in[13];
    const float* b2   = (const float*)d_in[14];
    const float* rw1  = (const float*)d_in[15];
    const float* rb1  = (const float*)d_in[16];
    const float* rw2  = (const float*)d_in[17];
    const float* rb2  = (const float*)d_in[18];
    const float* dw   = (const float*)d_in[19];
    const float* db   = (const float*)d_in[20];
    const float* cw   = (const float*)d_in[21];
    const float* cb   = (const float*)d_in[22];
    float* out = (float*)d_out;

    int N = in_sizes[0] / 128;
    int E = in_sizes[1] / 2;

    static bool attr_set = false;
    if (!attr_set) {
        cudaFuncSetAttribute(k_gemm1_hmma, cudaFuncAttributeMaxDynamicSharedMemorySize, SM_TOT);
        cudaFuncSetAttribute(k_gemm2_hmma, cudaFuncAttributeMaxDynamicSharedMemorySize, SM2_TOT);
        attr_set = true;
    }

    // fused adjacency build + W1/W2 prep
    k_fill_prep<<<80 + (E + 255) / 256, 256>>>(ei, W1, W2, E);

    // layer 1
    k_gemm1_hmma<<<(N + 127) / 128, 256, SM_TOT>>>(x, as1, ad1, N);
    k_gat1<<<(N * 32 + 255) / 256, 256>>>(b1, bng, bnb, bnm, bnv, N);

    // layer 2
    k_gemm2_hmma<<<(N + 63) / 64, 256, SM2_TOT>>>(as2, ad2, N);
    k_gat2<<<(N * 32 + 255) / 256, 256>>>(b2, N);

    k_final<<<(N + 255) / 256, 256>>>(ctx, rw1, rb1, rw2, rb2, dw, db, cw, cb,
                                      out, N);
}

// round 10
// speedup vs baseline: 1.3488x; 1.0373x over previous
#include <cuda_runtime.h>
#include <cuda_bf16.h>
#include <math.h>

#define MAXN 100000
#define CAP  128
#define NEG_SLOPE 0.2f
#define BN_EPS 1e-5f
#define RECON_W 0.1f

// ---------------- scratch (device globals) ----------------------------------
__device__ float g_h1 [MAXN * 128];   // x @ W1
__device__ float g_h1p[MAXN * 128];   // after GAT1 + BN + ELU
__device__ float g_h2 [MAXN * 32];    // h1p @ W2
__device__ float g_o2 [MAXN * 32];    // after GAT2 + bias
__device__ float g_as1[MAXN * 4];
__device__ float g_ad1[MAXN * 4];
__device__ float g_as2[MAXN];
__device__ float g_ad2[MAXN];
__device__ int   g_deg[MAXN];         // zeroed invariant: reset by k_gat2
__device__ int   g_csr[MAXN * CAP];   // per-dst src lists (bucketed)
__device__ __nv_bfloat16 g_w1hi[128 * 136];  // W1^T bf16 hi, n-major padded
__device__ __nv_bfloat16 g_w1lo[128 * 136];
__device__ __nv_bfloat16 g_w2hi[32 * 136];   // W2^T bf16 hi, n-major padded
__device__ __nv_bfloat16 g_w2lo[32 * 136];

__device__ __forceinline__ unsigned s2u(const void* p) {
    unsigned a;
    asm("{ .reg .u64 t; cvta.to.shared.u64 t, %1; cvt.u32.u64 %0, t; }" : "=r"(a) : "l"(p));
    return a;
}

#define LDSM4(f, addr) \
    asm volatile("ldmatrix.sync.aligned.m8n8.x4.shared.b16 {%0,%1,%2,%3}, [%4];" \
        : "=r"((f)[0]),"=r"((f)[1]),"=r"((f)[2]),"=r"((f)[3]) : "r"(addr))

#define MMA_BF16(dd, a, b0, b1) \
    asm volatile("mma.sync.aligned.m16n8k16.row.col.f32.bf16.bf16.f32 " \
        "{%0,%1,%2,%3}, {%4,%5,%6,%7}, {%8,%9}, {%0,%1,%2,%3};" \
        : "+f"((dd)[0]),"+f"((dd)[1]),"+f"((dd)[2]),"+f"((dd)[3]) \
        : "r"((a)[0]),"r"((a)[1]),"r"((a)[2]),"r"((a)[3]), "r"(b0),"r"(b1))

// ---------------- W1/W2 prep (tiny, runs before gemm1) -----------------------
__global__ void k_prep_w(const float* __restrict__ W1, const float* __restrict__ W2) {
    int b = blockIdx.x;
    if (b < 64) {                       // W1: [128,128] k-major -> [n][136]
        int i = b * 256 + threadIdx.x;
        int k = i >> 7, n = i & 127;
        float v = W1[i];
        __nv_bfloat16 hi = __float2bfloat16(v);
        __nv_bfloat16 lo = __float2bfloat16(v - __bfloat162float(hi));
        g_w1hi[n * 136 + k] = hi;
        g_w1lo[n * 136 + k] = lo;
    } else {                            // W2: [128,32] k-major -> [n][136]
        int i = (b - 64) * 256 + threadIdx.x;
        int k = i >> 5, n = i & 31;
        float v = W2[i];
        __nv_bfloat16 hi = __float2bfloat16(v);
        __nv_bfloat16 lo = __float2bfloat16(v - __bfloat162float(hi));
        g_w2hi[n * 136 + k] = hi;
        g_w2lo[n * 136 + k] = lo;
    }
}

// ============================================================================
// GEMM1 via mma.sync bf16 (3-chain hi/lo) + fused alpha1 + overlapped edge
// fill (tail blocks). Split-K, 2 phases. 256 threads, 128 rows/CTA.
// ============================================================================
#define SMH_ELE (128 * 72)
#define SM_TOT  (4 * SMH_ELE * 2 + 1024)

__global__ __launch_bounds__(256) void k_gemm1_hmma(
    const float* __restrict__ x,
    const float* __restrict__ avs, const float* __restrict__ avd,
    const int* __restrict__ ei, int N, int E, int nb1)
{
    // ---- tail blocks: edge fill (independent of GEMM) ----
    if (blockIdx.x >= nb1) {
        int e = (blockIdx.x - nb1) * 256 + threadIdx.x;
        if (e < E) {
            int s = ei[e], d = ei[E + e];
            int pos = atomicAdd(&g_deg[d], 1);
            if (pos < CAP) g_csr[d * CAP + pos] = s;
        }
        return;
    }

    extern __shared__ char sm[];
    __nv_bfloat16* Ahi = (__nv_bfloat16*)sm;
    __nv_bfloat16* Alo = Ahi + SMH_ELE;
    __nv_bfloat16* Whi = Alo + SMH_ELE;
    __nv_bfloat16* Wlo = Whi + SMH_ELE;
    float* s_as = (float*)(Wlo + SMH_ELE);
    float* s_ad = s_as + 128;

    int t = threadIdx.x;
    int r0 = blockIdx.x * 128;
    int wid = t >> 5, lane = t & 31;
    int j = lane >> 3, rin = lane & 7;

    if (t < 128) { s_as[t] = avs[t]; s_ad[t] = avd[t]; }

    int arow = t >> 1, ac0 = (t & 1) * 32;
    int gr_s = r0 + arow;
    bool aval = gr_s < N;
    int wn = t >> 1, wk0 = (t & 1) * 32;

    unsigned aOff = ((unsigned)((wid * 16 + (j & 1) * 8 + rin) * 72 + (j >> 1) * 8)) * 2;
    unsigned bOff = ((unsigned)(((j >> 1) * 8 + rin) * 72 + (j & 1) * 8)) * 2;
    unsigned aHiB = s2u(Ahi) + aOff, aLoB = s2u(Alo) + aOff;
    unsigned wHiB = s2u(Whi) + bOff, wLoB = s2u(Wlo) + bOff;

    float d[16][4];
#pragma unroll
    for (int i = 0; i < 16; i++)
#pragma unroll
        for (int q = 0; q < 4; q++) d[i][q] = 0.f;

#pragma unroll 1
    for (int half = 0; half < 2; half++) {
        if (half) __syncthreads();
        {
            const float* xr = x + (size_t)gr_s * 128 + half * 64 + ac0;
#pragma unroll
            for (int c = 0; c < 32; c += 4) {
                float4 v = aval ? *(const float4*)(xr + c) : make_float4(0, 0, 0, 0);
                float f[4] = {v.x, v.y, v.z, v.w};
                __nv_bfloat16 h[4], l[4];
#pragma unroll
                for (int q = 0; q < 4; q++) {
                    h[q] = __float2bfloat16(f[q]);
                    l[q] = __float2bfloat16(f[q] - __bfloat162float(h[q]));
                }
                int eo = arow * 72 + ac0 + c;
                *(__nv_bfloat162*)&Ahi[eo]     = __nv_bfloat162(h[0], h[1]);
                *(__nv_bfloat162*)&Ahi[eo + 2] = __nv_bfloat162(h[2], h[3]);
                *(__nv_bfloat162*)&Alo[eo]     = __nv_bfloat162(l[0], l[1]);
                *(__nv_bfloat162*)&Alo[eo + 2] = __nv_bfloat162(l[2], l[3]);
            }
        }
        {
#pragma unroll
            for (int q = 0; q < 4; q++) {
                int so = wn * 136 + half * 64 + wk0 + q * 8;
                int doff = wn * 72 + wk0 + q * 8;
                *(float4*)&Whi[doff] = *(const float4*)&g_w1hi[so];
                *(float4*)&Wlo[doff] = *(const float4*)&g_w1lo[so];
            }
        }
        __syncthreads();

#pragma unroll
        for (int ks = 0; ks < 4; ks++) {
            unsigned ah[4], al[4];
            LDSM4(ah, aHiB + ks * 32);
            LDSM4(al, aLoB + ks * 32);
#pragma unroll
            for (int p = 0; p < 8; p++) {
                unsigned bh[4], bl[4];
                LDSM4(bh, wHiB + p * 2304 + ks * 32);
                LDSM4(bl, wLoB + p * 2304 + ks * 32);
                MMA_BF16(d[2*p],     ah, bh[0], bh[1]);
                MMA_BF16(d[2*p + 1], ah, bh[2], bh[3]);
                MMA_BF16(d[2*p],     al, bh[0], bh[1]);
                MMA_BF16(d[2*p + 1], al, bh[2], bh[3]);
                MMA_BF16(d[2*p],     ah, bl[0], bl[1]);
                MMA_BF16(d[2*p + 1], ah, bl[2], bl[3]);
            }
        }
    }

    int g = lane >> 2, t4 = lane & 3;
    int rA = r0 + wid * 16 + g, rB = rA + 8;
    float psA[4] = {0,0,0,0}, pdA[4] = {0,0,0,0};
    float psB[4] = {0,0,0,0}, pdB[4] = {0,0,0,0};
#pragma unroll
    for (int nt = 0; nt < 16; nt++) {
        int n0 = nt * 8 + 2 * t4;
        float w0s = s_as[n0], w1s = s_as[n0 + 1];
        float w0d = s_ad[n0], w1d = s_ad[n0 + 1];
        int h = nt >> 2;
        psA[h] = fmaf(d[nt][0], w0s, fmaf(d[nt][1], w1s, psA[h]));
        pdA[h] = fmaf(d[nt][0], w0d, fmaf(d[nt][1], w1d, pdA[h]));
        psB[h] = fmaf(d[nt][2], w0s, fmaf(d[nt][3], w1s, psB[h]));
        pdB[h] = fmaf(d[nt][2], w0d, fmaf(d[nt][3], w1d, pdB[h]));
        if (rA < N) *(float2*)&g_h1[(size_t)rA * 128 + n0] = make_float2(d[nt][0], d[nt][1]);
        if (rB < N) *(float2*)&g_h1[(size_t)rB * 128 + n0] = make_float2(d[nt][2], d[nt][3]);
    }
#pragma unroll
    for (int h = 0; h < 4; h++) {
        psA[h] += __shfl_xor_sync(0xffffffffu, psA[h], 1);
        pdA[h] += __shfl_xor_sync(0xffffffffu, pdA[h], 1);
        psB[h] += __shfl_xor_sync(0xffffffffu, psB[h], 1);
        pdB[h] += __shfl_xor_sync(0xffffffffu, pdB[h], 1);
        psA[h] += __shfl_xor_sync(0xffffffffu, psA[h], 2);
        pdA[h] += __shfl_xor_sync(0xffffffffu, pdA[h], 2);
        psB[h] += __shfl_xor_sync(0xffffffffu, psB[h], 2);
        pdB[h] += __shfl_xor_sync(0xffffffffu, pdB[h], 2);
    }
    if (t4 == 0) {
        if (rA < N) {
#pragma unroll
            for (int h = 0; h < 4; h++) { g_as1[rA*4 + h] = psA[h]; g_ad1[rA*4 + h] = pdA[h]; }
        }
        if (rB < N) {
#pragma unroll
            for (int h = 0; h < 4; h++) { g_as1[rB*4 + h] = psB[h]; g_ad1[rB*4 + h] = pdB[h]; }
        }
    }
}

// ============================================================================
// GEMM2 via mma.sync bf16 (3-chain hi/lo) + fused alpha2. 64 rows/CTA.
// ============================================================================
#define SM2A_ELE (64 * 72)
#define SM2W_ELE (32 * 72)
#define SM2_TOT  (2 * SM2A_ELE * 2 + 2 * SM2W_ELE * 2 + 2 * 32 * 4 + 2 * 128 * 4)

__global__ __launch_bounds__(256) void k_gemm2_hmma(
    const float* __restrict__ avs, const float* __restrict__ avd, int N)
{
    extern __shared__ char sm[];
    __nv_bfloat16* Ahi = (__nv_bfloat16*)sm;
    __nv_bfloat16* Alo = Ahi + SM2A_ELE;
    __nv_bfloat16* Whi = Alo + SM2A_ELE;
    __nv_bfloat16* Wlo = Whi + SM2W_ELE;
    float* s_as = (float*)(Wlo + SM2W_ELE);
    float* s_ad = s_as + 32;
    float* ps_part = s_ad + 32;        // [64][2]
    float* pd_part = ps_part + 128;    // [64][2]

    int t = threadIdx.x;
    int r0 = blockIdx.x * 64;
    int wid = t >> 5, lane = t & 31;
    int j = lane >> 3, rin = lane & 7;

    if (t < 32) { s_as[t] = avs[t]; s_ad[t] = avd[t]; }

    int arow = t >> 2, ac0 = (t & 3) * 16;
    int gr_s = r0 + arow;
    bool aval = gr_s < N;
    int wn = t >> 3, wk0 = (t & 7) * 8;

    unsigned aOff = ((unsigned)(((wid >> 1) * 16 + (j & 1) * 8 + rin) * 72 + (j >> 1) * 8)) * 2;
    unsigned bOff = ((unsigned)(((wid & 1) * 16 + (j >> 1) * 8 + rin) * 72 + (j & 1) * 8)) * 2;
    unsigned aHiB = s2u(Ahi) + aOff, aLoB = s2u(Alo) + aOff;
    unsigned wHiB = s2u(Whi) + bOff, wLoB = s2u(Wlo) + bOff;

    float d[2][4];
#pragma unroll
    for (int i = 0; i < 2; i++)
#pragma unroll
        for (int q = 0; q < 4; q++) d[i][q] = 0.f;

#pragma unroll 1
    for (int half = 0; half < 2; half++) {
        if (half) __syncthreads();
        {
            const float* xr = g_h1p + (size_t)gr_s * 128 + half * 64 + ac0;
#pragma unroll
            for (int c = 0; c < 16; c += 4) {
                float4 v = aval ? *(const float4*)(xr + c) : make_float4(0, 0, 0, 0);
                float f[4] = {v.x, v.y, v.z, v.w};
                __nv_bfloat16 h[4], l[4];
#pragma unroll
                for (int q = 0; q < 4; q++) {
                    h[q] = __float2bfloat16(f[q]);
                    l[q] = __float2bfloat16(f[q] - __bfloat162float(h[q]));
                }
                int eo = arow * 72 + ac0 + c;
                *(__nv_bfloat162*)&Ahi[eo]     = __nv_bfloat162(h[0], h[1]);
                *(__nv_bfloat162*)&Ahi[eo + 2] = __nv_bfloat162(h[2], h[3]);
                *(__nv_bfloat162*)&Alo[eo]     = __nv_bfloat162(l[0], l[1]);
                *(__nv_bfloat162*)&Alo[eo + 2] = __nv_bfloat162(l[2], l[3]);
            }
        }
        {
            int so = wn * 136 + half * 64 + wk0;
            int doff = wn * 72 + wk0;
            *(float4*)&Whi[doff] = *(const float4*)&g_w2hi[so];
            *(float4*)&Wlo[doff] = *(const float4*)&g_w2lo[so];
        }
        __syncthreads();

#pragma unroll
        for (int ks = 0; ks < 4; ks++) {
            unsigned ah[4], al[4], bh[4], bl[4];
            LDSM4(ah, aHiB + ks * 32);
            LDSM4(al, aLoB + ks * 32);
            LDSM4(bh, wHiB + ks * 32);
            LDSM4(bl, wLoB + ks * 32);
            MMA_BF16(d[0], ah, bh[0], bh[1]);
            MMA_BF16(d[1], ah, bh[2], bh[3]);
            MMA_BF16(d[0], al, bh[0], bh[1]);
            MMA_BF16(d[1], al, bh[2], bh[3]);
            MMA_BF16(d[0], ah, bl[0], bl[1]);
            MMA_BF16(d[1], ah, bl[2], bl[3]);
        }
    }

    int g = lane >> 2, t4 = lane & 3;
    int lA = (wid >> 1) * 16 + g, lB = lA + 8;
    int rA = r0 + lA, rB = r0 + lB;
    int nbase = (wid & 1) * 16;
    float psA = 0.f, pdA = 0.f, psB = 0.f, pdB = 0.f;
#pragma unroll
    for (int nt = 0; nt < 2; nt++) {
        int n0 = nbase + nt * 8 + 2 * t4;
        float w0s = s_as[n0], w1s = s_as[n0 + 1];
        float w0d = s_ad[n0], w1d = s_ad[n0 + 1];
        psA = fmaf(d[nt][0], w0s, fmaf(d[nt][1], w1s, psA));
        pdA = fmaf(d[nt][0], w0d, fmaf(d[nt][1], w1d, pdA));
        psB = fmaf(d[nt][2], w0s, fmaf(d[nt][3], w1s, psB));
        pdB = fmaf(d[nt][2], w0d, fmaf(d[nt][3], w1d, pdB));
        if (rA < N) *(float2*)&g_h2[(size_t)rA * 32 + n0] = make_float2(d[nt][0], d[nt][1]);
        if (rB < N) *(float2*)&g_h2[(size_t)rB * 32 + n0] = make_float2(d[nt][2], d[nt][3]);
    }
    psA += __shfl_xor_sync(0xffffffffu, psA, 1);
    pdA += __shfl_xor_sync(0xffffffffu, pdA, 1);
    psB += __shfl_xor_sync(0xffffffffu, psB, 1);
    pdB += __shfl_xor_sync(0xffffffffu, pdB, 1);
    psA += __shfl_xor_sync(0xffffffffu, psA, 2);
    pdA += __shfl_xor_sync(0xffffffffu, pdA, 2);
    psB += __shfl_xor_sync(0xffffffffu, psB, 2);
    pdB += __shfl_xor_sync(0xffffffffu, pdB, 2);
    if (t4 == 0) {
        int nh = wid & 1;
        ps_part[lA * 2 + nh] = psA;  pd_part[lA * 2 + nh] = pdA;
        ps_part[lB * 2 + nh] = psB;  pd_part[lB * 2 + nh] = pdB;
    }
    __syncthreads();
    if (t < 64) {
        int gr = r0 + t;
        if (gr < N) {
            g_as2[gr] = ps_part[t * 2] + ps_part[t * 2 + 1];
            g_ad2[gr] = pd_part[t * 2] + pd_part[t * 2 + 1];
        }
    }
}

// ---------------- GAT1 gather: warp per dst node -----------------------------
__global__ __launch_bounds__(256) void k_gat1(
    const float* __restrict__ b1,
    const float* __restrict__ bg, const float* __restrict__ bb,
    const float* __restrict__ bm, const float* __restrict__ bv, int N)
{
    int gw   = (blockIdx.x * blockDim.x + threadIdx.x) >> 5;
    int lane = threadIdx.x & 31;
    if (gw >= N) return;
    int d    = gw;
    int head = lane >> 3;

    float adv = __ldg(&g_ad1[d * 4 + head]);

    float ts = __ldg(&g_as1[d * 4 + head]) + adv;
    float wself = __expf(fmaxf(ts, NEG_SLOPE * ts));
    const char* h1b  = (const char*)g_h1 + lane * 16;
    const char* as1b = (const char*)g_as1 + head * 4;
    float4 hv = *(const float4*)(h1b + ((size_t)d << 9));
    float4 acc = make_float4(wself*hv.x, wself*hv.y, wself*hv.z, wself*hv.w);
    float wsum = wself;

    int deg = min(g_deg[d], CAP);
    const int* lst = &g_csr[d * CAP];
    for (int j0 = 0; j0 < deg; j0 += 32) {
        int sid = (j0 + lane < deg) ? lst[j0 + lane] : 0;
        int soff = sid << 9;                 // byte offset into g_h1
        int m = min(32, deg - j0);
#pragma unroll 4
        for (int jj = 0; jj < m; jj++) {
            int off = __shfl_sync(0xffffffffu, soff, jj);
            float av = __ldg((const float*)(as1b + ((unsigned)off >> 5)));
            float tt = av + adv;
            float we = __expf(fmaxf(tt, NEG_SLOPE * tt));
            float4 h = *(const float4*)(h1b + off);
            acc.x = fmaf(we, h.x, acc.x);
            acc.y = fmaf(we, h.y, acc.y);
            acc.z = fmaf(we, h.z, acc.z);
            acc.w = fmaf(we, h.w, acc.w);
            wsum += we;
        }
    }

    float inv = 1.f / wsum;
    float4 bc = *(const float4*)&b1[lane * 4];
    float4 g4 = *(const float4*)&bg[lane * 4];
    float4 b4 = *(const float4*)&bb[lane * 4];
    float4 m4 = *(const float4*)&bm[lane * 4];
    float4 v4 = *(const float4*)&bv[lane * 4];
    float4 o;
    o.x = (acc.x * inv + bc.x - m4.x) * rsqrtf(v4.x + BN_EPS) * g4.x + b4.x;
    o.y = (acc.y * inv + bc.y - m4.y) * rsqrtf(v4.y + BN_EPS) * g4.y + b4.y;
    o.z = (acc.z * inv + bc.z - m4.z) * rsqrtf(v4.z + BN_EPS) * g4.z + b4.z;
    o.w = (acc.w * inv + bc.w - m4.w) * rsqrtf(v4.w + BN_EPS) * g4.w + b4.w;
    o.x = o.x > 0.f ? o.x : expm1f(o.x);
    o.y = o.y > 0.f ? o.y : expm1f(o.y);
    o.z = o.z > 0.f ? o.z : expm1f(o.z);
    o.w = o.w > 0.f ? o.w : expm1f(o.w);
    *(float4*)&g_h1p[(size_t)d * 128 + lane * 4] = o;
}

// ---------------- GAT2 gather: warp per dst node (C=32, 1 head) --------------
__global__ __launch_bounds__(256) void k_gat2(const float* __restrict__ b2, int N) {
    int gw   = (blockIdx.x * blockDim.x + threadIdx.x) >> 5;
    int lane = threadIdx.x & 31;
    if (gw >= N) return;
    int d = gw;

    float adv = __ldg(&g_ad2[d]);
    float ts = __ldg(&g_as2[d]) + adv;
    float w = __expf(fmaxf(ts, NEG_SLOPE * ts));
    const char* h2b = (const char*)g_h2 + lane * 4;
    float acc = w * *(const float*)(h2b + ((size_t)d << 7));
    float wsum = w;

    int deg = min(g_deg[d], CAP);
    const int* lst = &g_csr[d * CAP];
    for (int j0 = 0; j0 < deg; j0 += 32) {
        int m = min(32, deg - j0);
        int sid = (lane < m) ? lst[j0 + lane] : 0;
        int soff = sid << 7;
        float tt = __ldg(&g_as2[sid]) + adv;
        float wl = (lane < m) ? __expf(fmaxf(tt, NEG_SLOPE * tt)) : 0.f;
#pragma unroll 4
        for (int jj = 0; jj < m; jj++) {
            int off  = __shfl_sync(0xffffffffu, soff, jj);
            float we = __shfl_sync(0xffffffffu, wl, jj);
            acc = fmaf(we, *(const float*)(h2b + off), acc);
            wsum += we;
        }
    }
    g_o2[(size_t)d * 32 + lane] = acc / wsum + __ldg(&b2[lane]);
    if (lane == 0) g_deg[d] = 0;
}

// ---------------- final: per-node MLP tail + log_softmax ---------------------
__global__ void k_final(const float* __restrict__ ctx,
                        const float* __restrict__ rw1, const float* __restrict__ rb1,
                        const float* __restrict__ rw2, const float* __restrict__ rb2,
                        const float* __restrict__ dw,  const float* __restrict__ db,
                        const float* __restrict__ cw,  const float* __restrict__ cb,
                        float* __restrict__ out, int N) {
    __shared__ float sw[2666];
    int t = threadIdx.x;
    for (int i = t; i < 192;  i += 256) sw[i]        = rw1[i];
    for (int i = t; i < 32;   i += 256) sw[192 + i]  = rb1[i];
    for (int i = t; i < 1024; i += 256) sw[224 + i]  = rw2[i];
    for (int i = t; i < 32;   i += 256) sw[1248 + i] = rb2[i];
    for (int i = t; i < 1024; i += 256) sw[1280 + i] = dw[i];
    for (int i = t; i < 32;   i += 256) sw[2304 + i] = db[i];
    for (int i = t; i < 320;  i += 256) sw[2336 + i] = cw[i];
    for (int i = t; i < 10;   i += 256) sw[2656 + i] = cb[i];
    __syncthreads();

    int n = blockIdx.x * 256 + t;
    if (n >= N) return;

    float c0 = ctx[n * 6 + 0], c1 = ctx[n * 6 + 1], c2 = ctx[n * 6 + 2];
    float c3 = ctx[n * 6 + 3], c4 = ctx[n * 6 + 4], c5 = ctx[n * 6 + 5];

    float t1[32];
#pragma unroll
    for (int j = 0; j < 32; j++) {
        float v = sw[192 + j];
        v = fmaf(c0, sw[0 * 32 + j], v);
        v = fmaf(c1, sw[1 * 32 + j], v);
        v = fmaf(c2, sw[2 * 32 + j], v);
        v = fmaf(c3, sw[3 * 32 + j], v);
        v = fmaf(c4, sw[4 * 32 + j], v);
        v = fmaf(c5, sw[5 * 32 + j], v);
        t1[j] = fmaxf(v, 0.f);
    }
    float ex[32];
#pragma unroll
    for (int j = 0; j < 32; j++) {
        float v = sw[1248 + j];
#pragma unroll
        for (int k = 0; k < 32; k++) v = fmaf(t1[k], sw[224 + k * 32 + j], v);
        ex[j] = v;
    }
    float comb[32];
#pragma unroll
    for (int j = 0; j < 32; j++) {
        float rec = sw[2304 + j];
#pragma unroll
        for (int k = 0; k < 32; k++) rec = fmaf(ex[k], sw[1280 + k * 32 + j], rec);
        comb[j] = g_o2[(size_t)n * 32 + j] + RECON_W * rec;
    }
    float lg[10];
#pragma unroll
    for (int c = 0; c < 10; c++) {
        float v = sw[2656 + c];
#pragma unroll
        for (int j = 0; j < 32; j++) v = fmaf(comb[j], sw[2336 + j * 10 + c], v);
        lg[c] = v;
    }
    float m = lg[0];
#pragma unroll
    for (int c = 1; c < 10; c++) m = fmaxf(m, lg[c]);
    float sum = 0.f;
#pragma unroll
    for (int c = 0; c < 10; c++) sum += expf(lg[c] - m);
    float lse = m + logf(sum);
#pragma unroll
    for (int c = 0; c < 10; c++) out[n * 10 + c] = lg[c] - lse;
#pragma unroll
    for (int j = 0; j < 32; j++) out[N * 10 + n * 32 + j] = ex[j];
}

// ---------------- launch ------------------------------------------------------
extern "C" void kernel_launch(void* const* d_in, const int* in_sizes, int n_in,
                              void* d_out, int out_size) {
    const float* x    = (const float*)d_in[0];
    const int*   ei   = (const int*)  d_in[1];
    const float* ctx  = (const float*)d_in[2];
    const float* W1   = (const float*)d_in[3];
    const float* as1  = (const float*)d_in[4];
    const float* ad1  = (const float*)d_in[5];
    const float* b1   = (const float*)d_in[6];
    const float* bng  = (const float*)d_in[7];
    const float* bnb  = (const float*)d_in[8];
    const float* bnm  = (const float*)d_in[9];
    const float* bnv  = (const float*)d_in[10];
    const float* W2   = (const float*)d_in[11];
    const float* as2  = (const float*)d_in[12];
    const float* ad2  = (const float*)d_in[13];
    const float* b2   = (const float*)d_in[14];
    const float* rw1  = (const float*)d_in[15];
    const float* rb1  = (const float*)d_in[16];
    const float* rw2  = (const float*)d_in[17];
    const float* rb2  = (const float*)d_in[18];
    const float* dw   = (const float*)d_in[19];
    const float* db   = (const float*)d_in[20];
    const float* cw   = (const float*)d_in[21];
    const float* cb   = (const float*)d_in[22];
    float* out = (float*)d_out;

    int N = in_sizes[0] / 128;
    int E = in_sizes[1] / 2;

    static bool attr_set = false;
    if (!attr_set) {
        cudaFuncSetAttribute(k_gemm1_hmma, cudaFuncAttributeMaxDynamicSharedMemorySize, SM_TOT);
        cudaFuncSetAttribute(k_gemm2_hmma, cudaFuncAttributeMaxDynamicSharedMemorySize, SM2_TOT);
        attr_set = true;
    }

    // W prep (tiny), then GEMM1 with overlapped edge fill in tail blocks
    k_prep_w<<<80, 256>>>(W1, W2);
    int nb1 = (N + 127) / 128;
    int nbf = (E + 255) / 256;
    k_gemm1_hmma<<<nb1 + nbf, 256, SM_TOT>>>(x, as1, ad1, ei, N, E, nb1);
    k_gat1<<<(N * 32 + 255) / 256, 256>>>(b1, bng, bnb, bnm, bnv, N);

    // layer 2
    k_gemm2_hmma<<<(N + 63) / 64, 256, SM2_TOT>>>(as2, ad2, N);
    k_gat2<<<(N * 32 + 255) / 256, 256>>>(b2, N);

    k_final<<<(N + 255) / 256, 256>>>(ctx, rw1, rb1, rw2, rb2, dw, db, cw, cb,
                                      out, N);
}